// round 12
// baseline (speedup 1.0000x reference)
#include <cuda_runtime.h>
#include <cuda_fp16.h>
#include <cstdint>

#define N_ENTITIES 100000
#define N_USERS    50000
#define N_ITEMS    30000
#define D          64
#define N_REL      16
#define N_FACTORS  4
#define N_CLUSTERS 4
#define N_EDGES    1500000
#define NNZ_IM     1000000
#define NNZ_ICM    1000000
#define N_HOPS     2
#define TMP        0.2f

#define N_SEGS     (N_ENTITIES + N_USERS + N_USERS)   // 200000
#define IM_SEG0    N_ENTITIES
#define ICM_SEG0   (N_ENTITIES + N_USERS)
#define IM_BASE    N_EDGES
#define ICM_BASE   (N_EDGES + NNZ_IM)
#define TOT_NNZ    (N_EDGES + NNZ_IM + NNZ_ICM)       // 3.5M
#define NNZ_IMICM  (NNZ_IM + NNZ_ICM)                 // 2M

#define SCAN_TILE  1024
#define N_TILES    ((N_SEGS + SCAN_TILE - 1) / SCAN_TILE)   // 196

#define CONV_N     (N_ENTITIES * D / 2)

// ---------------- scratch ----------------
__device__ float  g_att [N_ENTITIES * N_REL];
__device__ float  g_ucls[N_USERS * N_CLUSTERS];
__device__ __half g_ehA [N_ENTITIES * D];
__device__ __half g_ehB [N_ENTITIES * D];
__device__ float  g_u   [N_USERS * D];
__device__ float  g_relsum[D];

__device__ int   g_counts  [N_SEGS];
__device__ int   g_offsets [N_SEGS];
__device__ int   g_cursor  [N_SEGS];
__device__ int   g_tilesum [N_TILES];
__device__ int   g_tilebase[N_TILES];
__device__ int2  g_edge [N_EDGES];   // {tail | etype<<20, imp bits}
__device__ int2  g_im   [NNZ_IM];    // {col, val bits}
__device__ int2  g_icm  [NNZ_ICM];   // {col | cls<<16, val bits}

// ---------------- side-stream prep ----------------
__global__ void convert_kernel(const float2* __restrict__ e2, __half2* __restrict__ eh,
                               const float* __restrict__ rel) {
    int i = blockIdx.x * blockDim.x + threadIdx.x;
    if (i < CONV_N) eh[i] = __float22half2_rn(e2[i]);
    if (i < D) {
        float s = 0.f;
#pragma unroll
        for (int r = 0; r < N_REL; r++) s += rel[r * D + i];
        g_relsum[i] = s;
    }
}

// ---------------- build ----------------
__global__ void zero_counts_kernel() {
    int i = blockIdx.x * blockDim.x + threadIdx.x;
    if (i < N_SEGS) g_counts[i] = 0;
}

__global__ void count_kernel(const int* __restrict__ head,
                             const int* __restrict__ im_rows,
                             const int* __restrict__ icm_rows) {
    int i = blockIdx.x * blockDim.x + threadIdx.x;
    if (i < N_EDGES) {
        atomicAdd(&g_counts[head[i]], 1);
    } else if (i < N_EDGES + NNZ_IM) {
        atomicAdd(&g_counts[IM_SEG0 + im_rows[i - N_EDGES]], 1);
    } else if (i < TOT_NNZ) {
        atomicAdd(&g_counts[ICM_SEG0 + icm_rows[i - N_EDGES - NNZ_IM]], 1);
    }
}

__global__ void scanA_kernel() {
    __shared__ int s[SCAN_TILE];
    int idx = blockIdx.x * SCAN_TILE + threadIdx.x;
    s[threadIdx.x] = (idx < N_SEGS) ? g_counts[idx] : 0;
    __syncthreads();
    for (int off = SCAN_TILE / 2; off > 0; off >>= 1) {
        if (threadIdx.x < off) s[threadIdx.x] += s[threadIdx.x + off];
        __syncthreads();
    }
    if (threadIdx.x == 0) g_tilesum[blockIdx.x] = s[0];
}

__global__ void scanB_kernel() {
    __shared__ int s[256];
    int t = threadIdx.x;
    int v = (t < N_TILES) ? g_tilesum[t] : 0;
    s[t] = v;
    __syncthreads();
    for (int off = 1; off < 256; off <<= 1) {
        int w = (t >= off) ? s[t - off] : 0;
        __syncthreads();
        s[t] += w;
        __syncthreads();
    }
    if (t < N_TILES) g_tilebase[t] = s[t] - v;
}

__global__ void scanC_kernel() {
    __shared__ int s[SCAN_TILE];
    int t = threadIdx.x;
    int idx = blockIdx.x * SCAN_TILE + t;
    int v = (idx < N_SEGS) ? g_counts[idx] : 0;
    s[t] = v;
    __syncthreads();
    for (int off = 1; off < SCAN_TILE; off <<= 1) {
        int w = (t >= off) ? s[t - off] : 0;
        __syncthreads();
        s[t] += w;
        __syncthreads();
    }
    if (idx < N_SEGS) {
        int excl = g_tilebase[blockIdx.x] + s[t] - v;
        g_offsets[idx] = excl;
        g_cursor[idx]  = excl;
    }
}

__global__ void fill_edge_kernel(const int* __restrict__ head, const int* __restrict__ tail,
                                 const int* __restrict__ etype, const float* __restrict__ eimp) {
    int i = blockIdx.x * blockDim.x + threadIdx.x;
    if (i < N_EDGES) {
        int h = head[i];
        int pos = atomicAdd(&g_cursor[h], 1);
        g_edge[pos] = make_int2(tail[i] | (etype[i] << 20), __float_as_int(eimp[i]));
    }
}

__global__ void fill_imicm_kernel(const int* __restrict__ im_rows, const int* __restrict__ im_cols,
                                  const float* __restrict__ im_vals,
                                  const int* __restrict__ icm_rows, const int* __restrict__ icm_cols,
                                  const int* __restrict__ icm_cls, const float* __restrict__ icm_vals) {
    int i = blockIdx.x * blockDim.x + threadIdx.x;
    if (i < NNZ_IM) {
        int r = im_rows[i];
        int pos = atomicAdd(&g_cursor[IM_SEG0 + r], 1) - IM_BASE;
        g_im[pos] = make_int2(im_cols[i], __float_as_int(im_vals[i]));
    } else if (i < NNZ_IMICM) {
        int j = i - NNZ_IM;
        int r = icm_rows[j];
        int pos = atomicAdd(&g_cursor[ICM_SEG0 + r], 1) - ICM_BASE;
        g_icm[pos] = make_int2(icm_cols[j] | (icm_cls[j] << 16), __float_as_int(icm_vals[j]));
    }
}

// ---------------- hop-0 att+ucls (fp32 inputs) ----------------
__global__ void attucls0_kernel(const float* __restrict__ e, const float* __restrict__ u,
                                const float* __restrict__ rel, const float* __restrict__ w) {
    __shared__ float s_rel[N_REL * D];
    __shared__ float s_w[N_CLUSTERS * D];
    for (int i = threadIdx.x; i < N_REL * D; i += blockDim.x) s_rel[i] = rel[i];
    for (int i = threadIdx.x; i < N_CLUSTERS * D; i += blockDim.x) s_w[i] = w[i];
    __syncthreads();
    int i = blockIdx.x * blockDim.x + threadIdx.x;
    if (i < N_ENTITIES) {
        const float4* row = (const float4*)(e + (size_t)i * D);
        float acc[N_REL];
#pragma unroll
        for (int r = 0; r < N_REL; r++) acc[r] = 0.f;
#pragma unroll
        for (int k = 0; k < D / 4; k++) {
            float4 ev = row[k];
#pragma unroll
            for (int r = 0; r < N_REL; r++) {
                float4 rv = ((const float4*)(s_rel + r * D))[k];
                acc[r] += ev.x * rv.x + ev.y * rv.y + ev.z * rv.z + ev.w * rv.w;
            }
        }
        float mx = acc[0];
#pragma unroll
        for (int r = 1; r < N_REL; r++) mx = fmaxf(mx, acc[r]);
        float sum = 0.f;
#pragma unroll
        for (int r = 0; r < N_REL; r++) { acc[r] = expf(acc[r] - mx); sum += acc[r]; }
        float inv = 1.f / sum;
#pragma unroll
        for (int r = 0; r < N_REL; r++) g_att[(size_t)i * N_REL + r] = acc[r] * inv;
    } else if (i < N_ENTITIES + N_USERS) {
        int uidx = i - N_ENTITIES;
        const float4* row = (const float4*)(u + (size_t)uidx * D);
        float acc[N_CLUSTERS] = {0.f, 0.f, 0.f, 0.f};
#pragma unroll
        for (int k = 0; k < D / 4; k++) {
            float4 uv = row[k];
#pragma unroll
            for (int c = 0; c < N_CLUSTERS; c++) {
                float4 wv = ((const float4*)(s_w + c * D))[k];
                acc[c] += uv.x * wv.x + uv.y * wv.y + uv.z * wv.z + uv.w * wv.w;
            }
        }
        float mx = fmaxf(fmaxf(acc[0], acc[1]), fmaxf(acc[2], acc[3]));
        float sum = 0.f;
#pragma unroll
        for (int c = 0; c < N_CLUSTERS; c++) { acc[c] = expf(acc[c] - mx); sum += acc[c]; }
        float inv = 1.f / sum;
#pragma unroll
        for (int c = 0; c < N_CLUSTERS; c++) g_ucls[(size_t)uidx * N_CLUSTERS + c] = acc[c] * inv;
    }
}

// ---------------- hop-1 att (entity, fp16 source) ----------------
__global__ void att_e_kernel(const __half2* __restrict__ eh, const float* __restrict__ rel) {
    __shared__ float s_rel[N_REL * D];
    for (int i = threadIdx.x; i < N_REL * D; i += blockDim.x) s_rel[i] = rel[i];
    __syncthreads();
    int i = blockIdx.x * blockDim.x + threadIdx.x;
    if (i >= N_ENTITIES) return;
    const __half2* row = eh + (size_t)i * (D / 2);
    float acc[N_REL];
#pragma unroll
    for (int r = 0; r < N_REL; r++) acc[r] = 0.f;
#pragma unroll
    for (int k = 0; k < D / 2; k++) {
        float2 ev = __half22float2(row[k]);
#pragma unroll
        for (int r = 0; r < N_REL; r++) {
            float2 rv = ((const float2*)(s_rel + r * D))[k];
            acc[r] += ev.x * rv.x + ev.y * rv.y;
        }
    }
    float mx = acc[0];
#pragma unroll
    for (int r = 1; r < N_REL; r++) mx = fmaxf(mx, acc[r]);
    float sum = 0.f;
#pragma unroll
    for (int r = 0; r < N_REL; r++) { acc[r] = expf(acc[r] - mx); sum += acc[r]; }
    float inv = 1.f / sum;
#pragma unroll
    for (int r = 0; r < N_REL; r++) g_att[(size_t)i * N_REL + r] = acc[r] * inv;
}

// ---------------- hop-1 ucls ----------------
__global__ void ucls_u_kernel(const float* __restrict__ u, const float* __restrict__ w) {
    __shared__ float s_w[N_CLUSTERS * D];
    for (int i = threadIdx.x; i < N_CLUSTERS * D; i += blockDim.x) s_w[i] = w[i];
    __syncthreads();
    int i = blockIdx.x * blockDim.x + threadIdx.x;
    if (i >= N_USERS) return;
    const float4* row = (const float4*)(u + (size_t)i * D);
    float acc[N_CLUSTERS] = {0.f, 0.f, 0.f, 0.f};
#pragma unroll
    for (int k = 0; k < D / 4; k++) {
        float4 uv = row[k];
#pragma unroll
        for (int c = 0; c < N_CLUSTERS; c++) {
            float4 wv = ((const float4*)(s_w + c * D))[k];
            acc[c] += uv.x * wv.x + uv.y * wv.y + uv.z * wv.z + uv.w * wv.w;
        }
    }
    float mx = fmaxf(fmaxf(acc[0], acc[1]), fmaxf(acc[2], acc[3]));
    float sum = 0.f;
#pragma unroll
    for (int c = 0; c < N_CLUSTERS; c++) { acc[c] = expf(acc[c] - mx); sum += acc[c]; }
    float inv = 1.f / sum;
#pragma unroll
    for (int c = 0; c < N_CLUSTERS; c++) g_ucls[(size_t)i * N_CLUSTERS + c] = acc[c] * inv;
}

// ---------------- entity gather: masked 8-wide blocks (no serial tail) ----------------
template <bool HOP0, bool LAST>
__global__ void __launch_bounds__(256)
ent_gather_kernel(const __half2* __restrict__ eh,
                  const float* __restrict__ rel,
                  __half2* __restrict__ eh_out,
                  const float2* __restrict__ base_ent, float2* __restrict__ res_ent) {
    __shared__ float2 s_rel[N_REL * 32];
    for (int i = threadIdx.x; i < N_REL * 32; i += blockDim.x)
        s_rel[i] = ((const float2*)rel)[i];
    __syncthreads();

    int warp = (blockIdx.x * blockDim.x + threadIdx.x) >> 5;
    int lane = threadIdx.x & 31;
    if (warp >= N_ENTITIES) return;
    float2 acc = make_float2(0.f, 0.f);

    int start = g_offsets[warp];
    int cnt   = g_counts[warp];
    const int2* ep = g_edge + start;
    const float* attrow = g_att + (size_t)warp * N_REL;
    for (int j = 0; j < cnt; j += 8) {
        int2 a[8]; float w[8]; int t[8], r[8];
#pragma unroll
        for (int q = 0; q < 8; q++) {
            int idx = j + q;
            bool val = idx < cnt;
            a[q] = ep[val ? idx : cnt - 1];
            t[q] = a[q].x & 0xFFFFF;
            r[q] = a[q].x >> 20;
            w[q] = val ? __int_as_float(a[q].y) * attrow[r[q]] : 0.f;
        }
        float2 v[8];
#pragma unroll
        for (int q = 0; q < 8; q++) v[q] = __half22float2(eh[(size_t)t[q] * 32 + lane]);
#pragma unroll
        for (int q = 0; q < 8; q++) {
            float2 qr = s_rel[r[q] * 32 + lane];
            acc.x += w[q] * v[q].x * qr.x;
            acc.y += w[q] * v[q].y * qr.y;
        }
    }
    float ss = acc.x * acc.x + acc.y * acc.y;
#pragma unroll
    for (int o = 16; o; o >>= 1) ss += __shfl_xor_sync(0xffffffffu, ss, o);
    float inv = 1.f / fmaxf(sqrtf(ss), 1e-12f);
    float2 o2 = make_float2(acc.x * inv, acc.y * inv);
    if (!LAST) eh_out[(size_t)warp * 32 + lane] = __float22half2_rn(o2);
    float2 cur = HOP0 ? base_ent[(size_t)warp * 32 + lane]
                      : res_ent[(size_t)warp * 32 + lane];
    cur.x += o2.x; cur.y += o2.y;
    res_ent[(size_t)warp * 32 + lane] = cur;
}

// ---------------- user gather: masked 8-wide blocks ----------------
template <bool HOP0, bool LAST>
__global__ void __launch_bounds__(256)
usr_gather_kernel(const __half2* __restrict__ eh,
                  float* __restrict__ u_out,
                  const float2* __restrict__ base_usr, float2* __restrict__ res_usr) {
    __shared__ float2 s_rs[32];
    if (threadIdx.x < 32) s_rs[threadIdx.x] = ((const float2*)g_relsum)[threadIdx.x];
    __syncthreads();

    int warp = (blockIdx.x * blockDim.x + threadIdx.x) >> 5;
    int lane = threadIdx.x & 31;
    if (warp >= N_USERS) return;
    int uidx = warp;
    float2 rs = s_rs[lane];
    const float* ucrow = g_ucls + (size_t)uidx * N_CLUSTERS;
    float2 acc = make_float2(0.f, 0.f);

    // im segment
    {
        int start = g_offsets[IM_SEG0 + uidx] - IM_BASE;
        int cnt   = g_counts[IM_SEG0 + uidx];
        const int2* ep = g_im + start;
        for (int j = 0; j < cnt; j += 8) {
            int2 a[8]; float w[8];
#pragma unroll
            for (int q = 0; q < 8; q++) {
                int idx = j + q;
                bool val = idx < cnt;
                a[q] = ep[val ? idx : cnt - 1];
                w[q] = val ? __int_as_float(a[q].y) : 0.f;
            }
            float2 v[8];
#pragma unroll
            for (int q = 0; q < 8; q++) v[q] = __half22float2(eh[(size_t)a[q].x * 32 + lane]);
#pragma unroll
            for (int q = 0; q < 8; q++) {
                acc.x += w[q] * v[q].x;
                acc.y += w[q] * v[q].y;
            }
        }
    }
    // icm segment (fused dw einsum)
    float2 acc2 = make_float2(0.f, 0.f);
    {
        int start = g_offsets[ICM_SEG0 + uidx] - ICM_BASE;
        int cnt   = g_counts[ICM_SEG0 + uidx];
        const int2* ep = g_icm + start;
        for (int j = 0; j < cnt; j += 8) {
            int2 a[8]; float w[8];
#pragma unroll
            for (int q = 0; q < 8; q++) {
                int idx = j + q;
                bool val = idx < cnt;
                a[q] = ep[val ? idx : cnt - 1];
                w[q] = val ? __int_as_float(a[q].y) * ucrow[a[q].x >> 16] : 0.f;
            }
            float2 v[8];
#pragma unroll
            for (int q = 0; q < 8; q++)
                v[q] = __half22float2(eh[(size_t)(a[q].x & 0xFFFF) * 32 + lane]);
#pragma unroll
            for (int q = 0; q < 8; q++) {
                acc2.x += w[q] * v[q].x;
                acc2.y += w[q] * v[q].y;
            }
        }
    }
    acc.x += acc2.x * rs.x;
    acc.y += acc2.y * rs.y;

    float ss = acc.x * acc.x + acc.y * acc.y;
#pragma unroll
    for (int o = 16; o; o >>= 1) ss += __shfl_xor_sync(0xffffffffu, ss, o);
    float inv = 1.f / fmaxf(sqrtf(ss), 1e-12f);
    float2 o2 = make_float2(acc.x * inv, acc.y * inv);
    if (!LAST) ((float2*)(u_out + (size_t)uidx * D))[lane] = o2;
    float2 cur = HOP0 ? base_usr[(size_t)uidx * 32 + lane]
                      : res_usr[(size_t)uidx * 32 + lane];
    cur.x += o2.x; cur.y += o2.y;
    res_usr[(size_t)uidx * 32 + lane] = cur;
}

// ---------------- cor loss ----------------
__global__ void cor_kernel(const float* __restrict__ dw, float* __restrict__ out) {
    float nt[N_FACTORS][N_REL];
#pragma unroll
    for (int c = 0; c < N_FACTORS; c++) {
        float ss = 0.f;
#pragma unroll
        for (int k = 0; k < N_REL; k++) { float x = dw[c * N_REL + k]; ss += x * x; }
        float inv = 1.f / fmaxf(sqrtf(ss), 1e-12f);
#pragma unroll
        for (int k = 0; k < N_REL; k++) nt[c][k] = dw[c * N_REL + k] * inv;
    }
    float loss = 0.f;
#pragma unroll
    for (int i = 0; i < N_FACTORS; i++) {
        float ssum = 0.f, diag = 0.f;
#pragma unroll
        for (int j = 0; j < N_FACTORS; j++) {
            float dot = 0.f;
#pragma unroll
            for (int k = 0; k < N_REL; k++) dot += nt[i][k] * nt[j][k];
            float s = expf(dot / TMP);
            ssum += s;
            if (i == j) diag = s;
        }
        loss -= logf(diag / ssum);
    }
    out[0] = loss;
}

// ---------------- launch ----------------
extern "C" void kernel_launch(void* const* d_in, const int* in_sizes, int n_in,
                              void* d_out, int out_size) {
    const float* user_emb     = (const float*)d_in[0];
    const float* entity_emb   = (const float*)d_in[1];
    const float* relation_emb = (const float*)d_in[3];
    const float* disen        = (const float*)d_in[4];
    const float* usr_cls_w    = (const float*)d_in[5];
    const float* edge_imp     = (const float*)d_in[6];
    const float* im_vals      = (const float*)d_in[7];
    const float* icm_vals     = (const float*)d_in[8];
    const int*   edge_index   = (const int*)d_in[9];
    const int*   edge_type    = (const int*)d_in[10];
    const int*   im_rows      = (const int*)d_in[11];
    const int*   im_cols      = (const int*)d_in[12];
    const int*   icm_cls      = (const int*)d_in[13];
    const int*   icm_rows     = (const int*)d_in[14];
    const int*   icm_cols     = (const int*)d_in[15];

    float* out     = (float*)d_out;
    float* out_ent = out;
    float* out_usr = out + (size_t)N_ENTITIES * D;
    float* out_cor = out + (size_t)N_ENTITIES * D + (size_t)N_USERS * D;

    __half *p_ehA, *p_ehB;
    float *p_u;
    cudaGetSymbolAddress((void**)&p_ehA, g_ehA);
    cudaGetSymbolAddress((void**)&p_ehB, g_ehB);
    cudaGetSymbolAddress((void**)&p_u, g_u);

    static cudaStream_t s1 = nullptr, s2 = nullptr;
    static cudaEvent_t ev_fork = nullptr, ev_prep = nullptr, ev_scan = nullptr,
                       ev_ent0 = nullptr, ev_usr = nullptr;
    if (s1 == nullptr) {
        cudaStreamCreateWithFlags(&s1, cudaStreamNonBlocking);
        cudaStreamCreateWithFlags(&s2, cudaStreamNonBlocking);
        cudaEventCreateWithFlags(&ev_fork, cudaEventDisableTiming);
        cudaEventCreateWithFlags(&ev_prep, cudaEventDisableTiming);
        cudaEventCreateWithFlags(&ev_scan, cudaEventDisableTiming);
        cudaEventCreateWithFlags(&ev_ent0, cudaEventDisableTiming);
        cudaEventCreateWithFlags(&ev_usr, cudaEventDisableTiming);
    }

    const int TPB = 256;
    unsigned ablocks  = (N_ENTITIES + N_USERS + TPB - 1) / TPB;
    unsigned eblocks  = (N_ENTITIES + TPB - 1) / TPB;
    unsigned ublocks  = (N_USERS + TPB - 1) / TPB;
    unsigned egblocks = (unsigned)(((long long)N_ENTITIES * 32 + TPB - 1) / TPB);
    unsigned ugblocks = (unsigned)(((long long)N_USERS * 32 + TPB - 1) / TPB);

    // ---- fork s1: convert+relsum, hop-0 att/ucls, cor ----
    cudaEventRecord(ev_fork, 0);
    cudaStreamWaitEvent(s1, ev_fork, 0);
    cudaStreamWaitEvent(s2, ev_fork, 0);
    convert_kernel<<<(CONV_N + TPB - 1) / TPB, TPB, 0, s1>>>(
        (const float2*)entity_emb, (__half2*)p_ehA, relation_emb);
    attucls0_kernel<<<ablocks, TPB, 0, s1>>>(entity_emb, user_emb, relation_emb, usr_cls_w);
    cor_kernel<<<1, 1, 0, s1>>>(disen, out_cor);
    cudaEventRecord(ev_prep, s1);

    // ---- main: count + scan ----
    zero_counts_kernel<<<(N_SEGS + TPB - 1) / TPB, TPB>>>();
    count_kernel<<<(TOT_NNZ + TPB - 1) / TPB, TPB>>>(edge_index, im_rows, icm_rows);
    scanA_kernel<<<N_TILES, SCAN_TILE>>>();
    scanB_kernel<<<1, 256>>>();
    scanC_kernel<<<N_TILES, SCAN_TILE>>>();
    cudaEventRecord(ev_scan, 0);

    // ---- s2: im/icm fill + user chain ----
    cudaStreamWaitEvent(s2, ev_scan, 0);
    fill_imicm_kernel<<<(NNZ_IMICM + TPB - 1) / TPB, TPB, 0, s2>>>(
        im_rows, im_cols, im_vals, icm_rows, icm_cols, icm_cls, icm_vals);
    cudaStreamWaitEvent(s2, ev_prep, 0);
    usr_gather_kernel<true, false><<<ugblocks, TPB, 0, s2>>>(
        (const __half2*)p_ehA, p_u, (const float2*)user_emb, (float2*)out_usr);
    ucls_u_kernel<<<ublocks, TPB, 0, s2>>>(p_u, usr_cls_w);

    // ---- main: edge fill + entity chain ----
    fill_edge_kernel<<<(N_EDGES + TPB - 1) / TPB, TPB>>>(
        edge_index, edge_index + N_EDGES, edge_type, edge_imp);
    cudaStreamWaitEvent(0, ev_prep, 0);
    ent_gather_kernel<true, false><<<egblocks, TPB>>>(
        (const __half2*)p_ehA, relation_emb, (__half2*)p_ehB,
        (const float2*)entity_emb, (float2*)out_ent);
    cudaEventRecord(ev_ent0, 0);

    // ---- s2: hop-1 user gather (needs ehB + ucls1) ----
    cudaStreamWaitEvent(s2, ev_ent0, 0);
    usr_gather_kernel<false, true><<<ugblocks, TPB, 0, s2>>>(
        (const __half2*)p_ehB, p_u, nullptr, (float2*)out_usr);
    cudaEventRecord(ev_usr, s2);

    // ---- main: hop-1 entity att + gather ----
    att_e_kernel<<<eblocks, TPB>>>((const __half2*)p_ehB, relation_emb);
    ent_gather_kernel<false, true><<<egblocks, TPB>>>(
        (const __half2*)p_ehB, relation_emb, (__half2*)p_ehA,
        nullptr, (float2*)out_ent);

    // ---- join all ----
    cudaStreamWaitEvent(0, ev_usr, 0);
}

// round 13
// speedup vs baseline: 1.1592x; 1.1592x over previous
#include <cuda_runtime.h>
#include <cuda_fp16.h>
#include <cstdint>

#define N_ENTITIES 100000
#define N_USERS    50000
#define N_ITEMS    30000
#define D          64
#define N_REL      16
#define N_FACTORS  4
#define N_CLUSTERS 4
#define N_EDGES    1500000
#define NNZ_IM     1000000
#define NNZ_ICM    1000000
#define N_HOPS     2
#define TMP        0.2f

#define N_SEGS     (N_ENTITIES + N_USERS + N_USERS)   // 200000
#define IM_SEG0    N_ENTITIES
#define ICM_SEG0   (N_ENTITIES + N_USERS)
#define IM_BASE    N_EDGES
#define ICM_BASE   (N_EDGES + NNZ_IM)
#define TOT_NNZ    (N_EDGES + NNZ_IM + NNZ_ICM)       // 3.5M
#define NNZ_IMICM  (NNZ_IM + NNZ_ICM)                 // 2M

#define SCAN_TILE  1024
#define N_TILES    ((N_SEGS + SCAN_TILE - 1) / SCAN_TILE)   // 196

#define CONV_N     (N_ENTITIES * D / 2)

// ---------------- scratch ----------------
__device__ float  g_att [N_ENTITIES * N_REL];
__device__ float  g_ucls[N_USERS * N_CLUSTERS];
__device__ __half g_ehA [N_ENTITIES * D];
__device__ __half g_ehB [N_ENTITIES * D];
__device__ float  g_u   [N_USERS * D];
__device__ float  g_relsum[D];

__device__ int   g_counts  [N_SEGS];
__device__ int   g_offsets [N_SEGS];
__device__ int   g_cursor  [N_SEGS];
__device__ int   g_tilesum [N_TILES];
__device__ int   g_tilebase[N_TILES];
__device__ int2  g_edge [N_EDGES];   // {tail | etype<<20, imp bits}
__device__ int2  g_im   [NNZ_IM];    // {col, val bits}
__device__ int2  g_icm  [NNZ_ICM];   // {col | cls<<16, val bits}

// ---------------- side-stream prep ----------------
__global__ void convert_kernel(const float2* __restrict__ e2, __half2* __restrict__ eh,
                               const float* __restrict__ rel) {
    int i = blockIdx.x * blockDim.x + threadIdx.x;
    if (i < CONV_N) eh[i] = __float22half2_rn(e2[i]);
    if (i < D) {
        float s = 0.f;
#pragma unroll
        for (int r = 0; r < N_REL; r++) s += rel[r * D + i];
        g_relsum[i] = s;
    }
}

// ---------------- build ----------------
__global__ void zero_counts_kernel() {
    int i = blockIdx.x * blockDim.x + threadIdx.x;
    if (i < N_SEGS) g_counts[i] = 0;
}

__global__ void count_kernel(const int* __restrict__ head,
                             const int* __restrict__ im_rows,
                             const int* __restrict__ icm_rows) {
    int i = blockIdx.x * blockDim.x + threadIdx.x;
    if (i < N_EDGES) {
        atomicAdd(&g_counts[head[i]], 1);
    } else if (i < N_EDGES + NNZ_IM) {
        atomicAdd(&g_counts[IM_SEG0 + im_rows[i - N_EDGES]], 1);
    } else if (i < TOT_NNZ) {
        atomicAdd(&g_counts[ICM_SEG0 + icm_rows[i - N_EDGES - NNZ_IM]], 1);
    }
}

__global__ void scanA_kernel() {
    __shared__ int s[SCAN_TILE];
    int idx = blockIdx.x * SCAN_TILE + threadIdx.x;
    s[threadIdx.x] = (idx < N_SEGS) ? g_counts[idx] : 0;
    __syncthreads();
    for (int off = SCAN_TILE / 2; off > 0; off >>= 1) {
        if (threadIdx.x < off) s[threadIdx.x] += s[threadIdx.x + off];
        __syncthreads();
    }
    if (threadIdx.x == 0) g_tilesum[blockIdx.x] = s[0];
}

__global__ void scanB_kernel() {
    __shared__ int s[256];
    int t = threadIdx.x;
    int v = (t < N_TILES) ? g_tilesum[t] : 0;
    s[t] = v;
    __syncthreads();
    for (int off = 1; off < 256; off <<= 1) {
        int w = (t >= off) ? s[t - off] : 0;
        __syncthreads();
        s[t] += w;
        __syncthreads();
    }
    if (t < N_TILES) g_tilebase[t] = s[t] - v;
}

__global__ void scanC_kernel() {
    __shared__ int s[SCAN_TILE];
    int t = threadIdx.x;
    int idx = blockIdx.x * SCAN_TILE + t;
    int v = (idx < N_SEGS) ? g_counts[idx] : 0;
    s[t] = v;
    __syncthreads();
    for (int off = 1; off < SCAN_TILE; off <<= 1) {
        int w = (t >= off) ? s[t - off] : 0;
        __syncthreads();
        s[t] += w;
        __syncthreads();
    }
    if (idx < N_SEGS) {
        int excl = g_tilebase[blockIdx.x] + s[t] - v;
        g_offsets[idx] = excl;
        g_cursor[idx]  = excl;
    }
}

__global__ void fill_edge_kernel(const int* __restrict__ head, const int* __restrict__ tail,
                                 const int* __restrict__ etype, const float* __restrict__ eimp) {
    int i = blockIdx.x * blockDim.x + threadIdx.x;
    if (i < N_EDGES) {
        int h = head[i];
        int pos = atomicAdd(&g_cursor[h], 1);
        g_edge[pos] = make_int2(tail[i] | (etype[i] << 20), __float_as_int(eimp[i]));
    }
}

__global__ void fill_imicm_kernel(const int* __restrict__ im_rows, const int* __restrict__ im_cols,
                                  const float* __restrict__ im_vals,
                                  const int* __restrict__ icm_rows, const int* __restrict__ icm_cols,
                                  const int* __restrict__ icm_cls, const float* __restrict__ icm_vals) {
    int i = blockIdx.x * blockDim.x + threadIdx.x;
    if (i < NNZ_IM) {
        int r = im_rows[i];
        int pos = atomicAdd(&g_cursor[IM_SEG0 + r], 1) - IM_BASE;
        g_im[pos] = make_int2(im_cols[i], __float_as_int(im_vals[i]));
    } else if (i < NNZ_IMICM) {
        int j = i - NNZ_IM;
        int r = icm_rows[j];
        int pos = atomicAdd(&g_cursor[ICM_SEG0 + r], 1) - ICM_BASE;
        g_icm[pos] = make_int2(icm_cols[j] | (icm_cls[j] << 16), __float_as_int(icm_vals[j]));
    }
}

// ---------------- hop-0 att+ucls (fp32 inputs) ----------------
__global__ void attucls0_kernel(const float* __restrict__ e, const float* __restrict__ u,
                                const float* __restrict__ rel, const float* __restrict__ w) {
    __shared__ float s_rel[N_REL * D];
    __shared__ float s_w[N_CLUSTERS * D];
    for (int i = threadIdx.x; i < N_REL * D; i += blockDim.x) s_rel[i] = rel[i];
    for (int i = threadIdx.x; i < N_CLUSTERS * D; i += blockDim.x) s_w[i] = w[i];
    __syncthreads();
    int i = blockIdx.x * blockDim.x + threadIdx.x;
    if (i < N_ENTITIES) {
        const float4* row = (const float4*)(e + (size_t)i * D);
        float acc[N_REL];
#pragma unroll
        for (int r = 0; r < N_REL; r++) acc[r] = 0.f;
#pragma unroll
        for (int k = 0; k < D / 4; k++) {
            float4 ev = row[k];
#pragma unroll
            for (int r = 0; r < N_REL; r++) {
                float4 rv = ((const float4*)(s_rel + r * D))[k];
                acc[r] += ev.x * rv.x + ev.y * rv.y + ev.z * rv.z + ev.w * rv.w;
            }
        }
        float mx = acc[0];
#pragma unroll
        for (int r = 1; r < N_REL; r++) mx = fmaxf(mx, acc[r]);
        float sum = 0.f;
#pragma unroll
        for (int r = 0; r < N_REL; r++) { acc[r] = expf(acc[r] - mx); sum += acc[r]; }
        float inv = 1.f / sum;
#pragma unroll
        for (int r = 0; r < N_REL; r++) g_att[(size_t)i * N_REL + r] = acc[r] * inv;
    } else if (i < N_ENTITIES + N_USERS) {
        int uidx = i - N_ENTITIES;
        const float4* row = (const float4*)(u + (size_t)uidx * D);
        float acc[N_CLUSTERS] = {0.f, 0.f, 0.f, 0.f};
#pragma unroll
        for (int k = 0; k < D / 4; k++) {
            float4 uv = row[k];
#pragma unroll
            for (int c = 0; c < N_CLUSTERS; c++) {
                float4 wv = ((const float4*)(s_w + c * D))[k];
                acc[c] += uv.x * wv.x + uv.y * wv.y + uv.z * wv.z + uv.w * wv.w;
            }
        }
        float mx = fmaxf(fmaxf(acc[0], acc[1]), fmaxf(acc[2], acc[3]));
        float sum = 0.f;
#pragma unroll
        for (int c = 0; c < N_CLUSTERS; c++) { acc[c] = expf(acc[c] - mx); sum += acc[c]; }
        float inv = 1.f / sum;
#pragma unroll
        for (int c = 0; c < N_CLUSTERS; c++) g_ucls[(size_t)uidx * N_CLUSTERS + c] = acc[c] * inv;
    }
}

// ---------------- hop-1 att (entity, fp16 source) ----------------
__global__ void att_e_kernel(const __half2* __restrict__ eh, const float* __restrict__ rel) {
    __shared__ float s_rel[N_REL * D];
    for (int i = threadIdx.x; i < N_REL * D; i += blockDim.x) s_rel[i] = rel[i];
    __syncthreads();
    int i = blockIdx.x * blockDim.x + threadIdx.x;
    if (i >= N_ENTITIES) return;
    const __half2* row = eh + (size_t)i * (D / 2);
    float acc[N_REL];
#pragma unroll
    for (int r = 0; r < N_REL; r++) acc[r] = 0.f;
#pragma unroll
    for (int k = 0; k < D / 2; k++) {
        float2 ev = __half22float2(row[k]);
#pragma unroll
        for (int r = 0; r < N_REL; r++) {
            float2 rv = ((const float2*)(s_rel + r * D))[k];
            acc[r] += ev.x * rv.x + ev.y * rv.y;
        }
    }
    float mx = acc[0];
#pragma unroll
    for (int r = 1; r < N_REL; r++) mx = fmaxf(mx, acc[r]);
    float sum = 0.f;
#pragma unroll
    for (int r = 0; r < N_REL; r++) { acc[r] = expf(acc[r] - mx); sum += acc[r]; }
    float inv = 1.f / sum;
#pragma unroll
    for (int r = 0; r < N_REL; r++) g_att[(size_t)i * N_REL + r] = acc[r] * inv;
}

// ---------------- hop-1 ucls ----------------
__global__ void ucls_u_kernel(const float* __restrict__ u, const float* __restrict__ w) {
    __shared__ float s_w[N_CLUSTERS * D];
    for (int i = threadIdx.x; i < N_CLUSTERS * D; i += blockDim.x) s_w[i] = w[i];
    __syncthreads();
    int i = blockIdx.x * blockDim.x + threadIdx.x;
    if (i >= N_USERS) return;
    const float4* row = (const float4*)(u + (size_t)i * D);
    float acc[N_CLUSTERS] = {0.f, 0.f, 0.f, 0.f};
#pragma unroll
    for (int k = 0; k < D / 4; k++) {
        float4 uv = row[k];
#pragma unroll
        for (int c = 0; c < N_CLUSTERS; c++) {
            float4 wv = ((const float4*)(s_w + c * D))[k];
            acc[c] += uv.x * wv.x + uv.y * wv.y + uv.z * wv.z + uv.w * wv.w;
        }
    }
    float mx = fmaxf(fmaxf(acc[0], acc[1]), fmaxf(acc[2], acc[3]));
    float sum = 0.f;
#pragma unroll
    for (int c = 0; c < N_CLUSTERS; c++) { acc[c] = expf(acc[c] - mx); sum += acc[c]; }
    float inv = 1.f / sum;
#pragma unroll
    for (int c = 0; c < N_CLUSTERS; c++) g_ucls[(size_t)i * N_CLUSTERS + c] = acc[c] * inv;
}

// ---------------- entity gather: 16-deep unroll + rolled remainder ----------------
template <bool HOP0, bool LAST>
__global__ void __launch_bounds__(256)
ent_gather_kernel(const __half2* __restrict__ eh,
                  const float* __restrict__ rel,
                  __half2* __restrict__ eh_out,
                  const float2* __restrict__ base_ent, float2* __restrict__ res_ent) {
    __shared__ float2 s_rel[N_REL * 32];
    for (int i = threadIdx.x; i < N_REL * 32; i += blockDim.x)
        s_rel[i] = ((const float2*)rel)[i];
    __syncthreads();

    int warp = (blockIdx.x * blockDim.x + threadIdx.x) >> 5;
    int lane = threadIdx.x & 31;
    if (warp >= N_ENTITIES) return;
    float2 acc = make_float2(0.f, 0.f);

    int start = g_offsets[warp];
    int cnt   = g_counts[warp];
    const int2* ep = g_edge + start;
    const float* attrow = g_att + (size_t)warp * N_REL;
    int j = 0;
    for (; j + 16 <= cnt; j += 16) {
        int2 a[16];
#pragma unroll
        for (int q = 0; q < 16; q++) a[q] = ep[j + q];
        float w[16];
        int t[16], r[16];
#pragma unroll
        for (int q = 0; q < 16; q++) {
            t[q] = a[q].x & 0xFFFFF;
            r[q] = a[q].x >> 20;
            w[q] = __int_as_float(a[q].y) * attrow[r[q]];
        }
        float2 v[16];
#pragma unroll
        for (int q = 0; q < 16; q++) v[q] = __half22float2(eh[(size_t)t[q] * 32 + lane]);
#pragma unroll
        for (int q = 0; q < 16; q++) {
            float2 qr = s_rel[r[q] * 32 + lane];
            acc.x += w[q] * v[q].x * qr.x;
            acc.y += w[q] * v[q].y * qr.y;
        }
    }
    for (; j + 8 <= cnt; j += 8) {
        int2 a[8];
#pragma unroll
        for (int q = 0; q < 8; q++) a[q] = ep[j + q];
        float w[8];
        int t[8], r[8];
#pragma unroll
        for (int q = 0; q < 8; q++) {
            t[q] = a[q].x & 0xFFFFF;
            r[q] = a[q].x >> 20;
            w[q] = __int_as_float(a[q].y) * attrow[r[q]];
        }
        float2 v[8];
#pragma unroll
        for (int q = 0; q < 8; q++) v[q] = __half22float2(eh[(size_t)t[q] * 32 + lane]);
#pragma unroll
        for (int q = 0; q < 8; q++) {
            float2 qr = s_rel[r[q] * 32 + lane];
            acc.x += w[q] * v[q].x * qr.x;
            acc.y += w[q] * v[q].y * qr.y;
        }
    }
    for (; j < cnt; j++) {
        int2 a = ep[j];
        int t = a.x & 0xFFFFF, r = a.x >> 20;
        float wv = __int_as_float(a.y) * attrow[r];
        float2 v = __half22float2(eh[(size_t)t * 32 + lane]);
        float2 q = s_rel[r * 32 + lane];
        acc.x += wv * v.x * q.x;
        acc.y += wv * v.y * q.y;
    }
    float ss = acc.x * acc.x + acc.y * acc.y;
#pragma unroll
    for (int o = 16; o; o >>= 1) ss += __shfl_xor_sync(0xffffffffu, ss, o);
    float inv = 1.f / fmaxf(sqrtf(ss), 1e-12f);
    float2 o2 = make_float2(acc.x * inv, acc.y * inv);
    if (!LAST) eh_out[(size_t)warp * 32 + lane] = __float22half2_rn(o2);
    float2 cur = HOP0 ? base_ent[(size_t)warp * 32 + lane]
                      : res_ent[(size_t)warp * 32 + lane];
    cur.x += o2.x; cur.y += o2.y;
    res_ent[(size_t)warp * 32 + lane] = cur;
}

// ---------------- user gather: 16-deep unroll + rolled remainder ----------------
template <bool HOP0, bool LAST>
__global__ void __launch_bounds__(256)
usr_gather_kernel(const __half2* __restrict__ eh,
                  float* __restrict__ u_out,
                  const float2* __restrict__ base_usr, float2* __restrict__ res_usr) {
    __shared__ float2 s_rs[32];
    if (threadIdx.x < 32) s_rs[threadIdx.x] = ((const float2*)g_relsum)[threadIdx.x];
    __syncthreads();

    int warp = (blockIdx.x * blockDim.x + threadIdx.x) >> 5;
    int lane = threadIdx.x & 31;
    if (warp >= N_USERS) return;
    int uidx = warp;
    float2 rs = s_rs[lane];
    const float* ucrow = g_ucls + (size_t)uidx * N_CLUSTERS;
    float2 acc = make_float2(0.f, 0.f);

    // im segment
    {
        int start = g_offsets[IM_SEG0 + uidx] - IM_BASE;
        int cnt   = g_counts[IM_SEG0 + uidx];
        const int2* ep = g_im + start;
        int j = 0;
        for (; j + 16 <= cnt; j += 16) {
            int2 a[16];
#pragma unroll
            for (int q = 0; q < 16; q++) a[q] = ep[j + q];
            float2 v[16];
#pragma unroll
            for (int q = 0; q < 16; q++) v[q] = __half22float2(eh[(size_t)a[q].x * 32 + lane]);
#pragma unroll
            for (int q = 0; q < 16; q++) {
                float w = __int_as_float(a[q].y);
                acc.x += w * v[q].x;
                acc.y += w * v[q].y;
            }
        }
        for (; j + 8 <= cnt; j += 8) {
            int2 a[8];
#pragma unroll
            for (int q = 0; q < 8; q++) a[q] = ep[j + q];
            float2 v[8];
#pragma unroll
            for (int q = 0; q < 8; q++) v[q] = __half22float2(eh[(size_t)a[q].x * 32 + lane]);
#pragma unroll
            for (int q = 0; q < 8; q++) {
                float w = __int_as_float(a[q].y);
                acc.x += w * v[q].x;
                acc.y += w * v[q].y;
            }
        }
        for (; j < cnt; j++) {
            int2 a = ep[j];
            float2 v = __half22float2(eh[(size_t)a.x * 32 + lane]);
            float w = __int_as_float(a.y);
            acc.x += w * v.x;
            acc.y += w * v.y;
        }
    }
    // icm segment (fused dw einsum)
    float2 acc2 = make_float2(0.f, 0.f);
    {
        int start = g_offsets[ICM_SEG0 + uidx] - ICM_BASE;
        int cnt   = g_counts[ICM_SEG0 + uidx];
        const int2* ep = g_icm + start;
        int j = 0;
        for (; j + 16 <= cnt; j += 16) {
            int2 a[16];
#pragma unroll
            for (int q = 0; q < 16; q++) a[q] = ep[j + q];
            float w[16];
#pragma unroll
            for (int q = 0; q < 16; q++)
                w[q] = __int_as_float(a[q].y) * ucrow[a[q].x >> 16];
            float2 v[16];
#pragma unroll
            for (int q = 0; q < 16; q++)
                v[q] = __half22float2(eh[(size_t)(a[q].x & 0xFFFF) * 32 + lane]);
#pragma unroll
            for (int q = 0; q < 16; q++) {
                acc2.x += w[q] * v[q].x;
                acc2.y += w[q] * v[q].y;
            }
        }
        for (; j + 8 <= cnt; j += 8) {
            int2 a[8];
#pragma unroll
            for (int q = 0; q < 8; q++) a[q] = ep[j + q];
            float w[8];
#pragma unroll
            for (int q = 0; q < 8; q++)
                w[q] = __int_as_float(a[q].y) * ucrow[a[q].x >> 16];
            float2 v[8];
#pragma unroll
            for (int q = 0; q < 8; q++)
                v[q] = __half22float2(eh[(size_t)(a[q].x & 0xFFFF) * 32 + lane]);
#pragma unroll
            for (int q = 0; q < 8; q++) {
                acc2.x += w[q] * v[q].x;
                acc2.y += w[q] * v[q].y;
            }
        }
        for (; j < cnt; j++) {
            int2 a = ep[j];
            int c = a.x & 0xFFFF, k = a.x >> 16;
            float w = __int_as_float(a.y) * ucrow[k];
            float2 v = __half22float2(eh[(size_t)c * 32 + lane]);
            acc2.x += w * v.x;
            acc2.y += w * v.y;
        }
    }
    acc.x += acc2.x * rs.x;
    acc.y += acc2.y * rs.y;

    float ss = acc.x * acc.x + acc.y * acc.y;
#pragma unroll
    for (int o = 16; o; o >>= 1) ss += __shfl_xor_sync(0xffffffffu, ss, o);
    float inv = 1.f / fmaxf(sqrtf(ss), 1e-12f);
    float2 o2 = make_float2(acc.x * inv, acc.y * inv);
    if (!LAST) ((float2*)(u_out + (size_t)uidx * D))[lane] = o2;
    float2 cur = HOP0 ? base_usr[(size_t)uidx * 32 + lane]
                      : res_usr[(size_t)uidx * 32 + lane];
    cur.x += o2.x; cur.y += o2.y;
    res_usr[(size_t)uidx * 32 + lane] = cur;
}

// ---------------- cor loss ----------------
__global__ void cor_kernel(const float* __restrict__ dw, float* __restrict__ out) {
    float nt[N_FACTORS][N_REL];
#pragma unroll
    for (int c = 0; c < N_FACTORS; c++) {
        float ss = 0.f;
#pragma unroll
        for (int k = 0; k < N_REL; k++) { float x = dw[c * N_REL + k]; ss += x * x; }
        float inv = 1.f / fmaxf(sqrtf(ss), 1e-12f);
#pragma unroll
        for (int k = 0; k < N_REL; k++) nt[c][k] = dw[c * N_REL + k] * inv;
    }
    float loss = 0.f;
#pragma unroll
    for (int i = 0; i < N_FACTORS; i++) {
        float ssum = 0.f, diag = 0.f;
#pragma unroll
        for (int j = 0; j < N_FACTORS; j++) {
            float dot = 0.f;
#pragma unroll
            for (int k = 0; k < N_REL; k++) dot += nt[i][k] * nt[j][k];
            float s = expf(dot / TMP);
            ssum += s;
            if (i == j) diag = s;
        }
        loss -= logf(diag / ssum);
    }
    out[0] = loss;
}

// ---------------- launch ----------------
extern "C" void kernel_launch(void* const* d_in, const int* in_sizes, int n_in,
                              void* d_out, int out_size) {
    const float* user_emb     = (const float*)d_in[0];
    const float* entity_emb   = (const float*)d_in[1];
    const float* relation_emb = (const float*)d_in[3];
    const float* disen        = (const float*)d_in[4];
    const float* usr_cls_w    = (const float*)d_in[5];
    const float* edge_imp     = (const float*)d_in[6];
    const float* im_vals      = (const float*)d_in[7];
    const float* icm_vals     = (const float*)d_in[8];
    const int*   edge_index   = (const int*)d_in[9];
    const int*   edge_type    = (const int*)d_in[10];
    const int*   im_rows      = (const int*)d_in[11];
    const int*   im_cols      = (const int*)d_in[12];
    const int*   icm_cls      = (const int*)d_in[13];
    const int*   icm_rows     = (const int*)d_in[14];
    const int*   icm_cols     = (const int*)d_in[15];

    float* out     = (float*)d_out;
    float* out_ent = out;
    float* out_usr = out + (size_t)N_ENTITIES * D;
    float* out_cor = out + (size_t)N_ENTITIES * D + (size_t)N_USERS * D;

    __half *p_ehA, *p_ehB;
    float *p_u;
    cudaGetSymbolAddress((void**)&p_ehA, g_ehA);
    cudaGetSymbolAddress((void**)&p_ehB, g_ehB);
    cudaGetSymbolAddress((void**)&p_u, g_u);

    static cudaStream_t s1 = nullptr, s2 = nullptr;
    static cudaEvent_t ev_fork = nullptr, ev_prep = nullptr, ev_scan = nullptr,
                       ev_ent0 = nullptr, ev_usr = nullptr;
    if (s1 == nullptr) {
        cudaStreamCreateWithFlags(&s1, cudaStreamNonBlocking);
        cudaStreamCreateWithFlags(&s2, cudaStreamNonBlocking);
        cudaEventCreateWithFlags(&ev_fork, cudaEventDisableTiming);
        cudaEventCreateWithFlags(&ev_prep, cudaEventDisableTiming);
        cudaEventCreateWithFlags(&ev_scan, cudaEventDisableTiming);
        cudaEventCreateWithFlags(&ev_ent0, cudaEventDisableTiming);
        cudaEventCreateWithFlags(&ev_usr, cudaEventDisableTiming);
    }

    const int TPB = 256;
    unsigned ablocks  = (N_ENTITIES + N_USERS + TPB - 1) / TPB;
    unsigned eblocks  = (N_ENTITIES + TPB - 1) / TPB;
    unsigned ublocks  = (N_USERS + TPB - 1) / TPB;
    unsigned egblocks = (unsigned)(((long long)N_ENTITIES * 32 + TPB - 1) / TPB);
    unsigned ugblocks = (unsigned)(((long long)N_USERS * 32 + TPB - 1) / TPB);

    // ---- fork s1: convert+relsum, hop-0 att/ucls, cor ----
    cudaEventRecord(ev_fork, 0);
    cudaStreamWaitEvent(s1, ev_fork, 0);
    cudaStreamWaitEvent(s2, ev_fork, 0);
    convert_kernel<<<(CONV_N + TPB - 1) / TPB, TPB, 0, s1>>>(
        (const float2*)entity_emb, (__half2*)p_ehA, relation_emb);
    attucls0_kernel<<<ablocks, TPB, 0, s1>>>(entity_emb, user_emb, relation_emb, usr_cls_w);
    cor_kernel<<<1, 1, 0, s1>>>(disen, out_cor);
    cudaEventRecord(ev_prep, s1);

    // ---- main: count + scan ----
    zero_counts_kernel<<<(N_SEGS + TPB - 1) / TPB, TPB>>>();
    count_kernel<<<(TOT_NNZ + TPB - 1) / TPB, TPB>>>(edge_index, im_rows, icm_rows);
    scanA_kernel<<<N_TILES, SCAN_TILE>>>();
    scanB_kernel<<<1, 256>>>();
    scanC_kernel<<<N_TILES, SCAN_TILE>>>();
    cudaEventRecord(ev_scan, 0);

    // ---- s2: im/icm fill + user chain ----
    cudaStreamWaitEvent(s2, ev_scan, 0);
    fill_imicm_kernel<<<(NNZ_IMICM + TPB - 1) / TPB, TPB, 0, s2>>>(
        im_rows, im_cols, im_vals, icm_rows, icm_cols, icm_cls, icm_vals);
    cudaStreamWaitEvent(s2, ev_prep, 0);
    usr_gather_kernel<true, false><<<ugblocks, TPB, 0, s2>>>(
        (const __half2*)p_ehA, p_u, (const float2*)user_emb, (float2*)out_usr);
    ucls_u_kernel<<<ublocks, TPB, 0, s2>>>(p_u, usr_cls_w);

    // ---- main: edge fill + entity chain ----
    fill_edge_kernel<<<(N_EDGES + TPB - 1) / TPB, TPB>>>(
        edge_index, edge_index + N_EDGES, edge_type, edge_imp);
    cudaStreamWaitEvent(0, ev_prep, 0);
    ent_gather_kernel<true, false><<<egblocks, TPB>>>(
        (const __half2*)p_ehA, relation_emb, (__half2*)p_ehB,
        (const float2*)entity_emb, (float2*)out_ent);
    cudaEventRecord(ev_ent0, 0);

    // ---- s2: hop-1 user gather (needs ehB + ucls1) ----
    cudaStreamWaitEvent(s2, ev_ent0, 0);
    usr_gather_kernel<false, true><<<ugblocks, TPB, 0, s2>>>(
        (const __half2*)p_ehB, p_u, nullptr, (float2*)out_usr);
    cudaEventRecord(ev_usr, s2);

    // ---- main: hop-1 entity att + gather ----
    att_e_kernel<<<eblocks, TPB>>>((const __half2*)p_ehB, relation_emb);
    ent_gather_kernel<false, true><<<egblocks, TPB>>>(
        (const __half2*)p_ehB, relation_emb, (__half2*)p_ehA,
        nullptr, (float2*)out_ent);

    // ---- join all ----
    cudaStreamWaitEvent(0, ev_usr, 0);
}

// round 14
// speedup vs baseline: 1.2390x; 1.0689x over previous
#include <cuda_runtime.h>
#include <cuda_fp16.h>
#include <cstdint>

#define N_ENTITIES 100000
#define N_USERS    50000
#define N_ITEMS    30000
#define D          64
#define N_REL      16
#define N_FACTORS  4
#define N_CLUSTERS 4
#define N_EDGES    1500000
#define NNZ_IM     1000000
#define NNZ_ICM    1000000
#define N_HOPS     2
#define TMP        0.2f

#define N_SEGS     (N_ENTITIES + N_USERS + N_USERS)   // 200000
#define IM_SEG0    N_ENTITIES
#define ICM_SEG0   (N_ENTITIES + N_USERS)
#define IM_BASE    N_EDGES
#define ICM_BASE   (N_EDGES + NNZ_IM)
#define TOT_NNZ    (N_EDGES + NNZ_IM + NNZ_ICM)       // 3.5M
#define NNZ_IMICM  (NNZ_IM + NNZ_ICM)                 // 2M

#define SCAN_TILE  1024
#define N_TILES    ((N_SEGS + SCAN_TILE - 1) / SCAN_TILE)   // 196

#define CONV_N     (N_ENTITIES * D / 2)

// ---------------- scratch ----------------
__device__ float  g_att [N_ENTITIES * N_REL];
__device__ float  g_ucls[N_USERS * N_CLUSTERS];
__device__ __half g_ehA [N_ENTITIES * D];
__device__ __half g_ehB [N_ENTITIES * D];
__device__ float  g_u   [N_USERS * D];
__device__ float  g_relsum[D];

__device__ int   g_counts  [N_SEGS];
__device__ int   g_offsets [N_SEGS];
__device__ int   g_cursor  [N_SEGS];
__device__ int   g_tilesum [N_TILES];
__device__ int   g_tilebase[N_TILES];
__device__ int2  g_edge [N_EDGES];   // {tail | etype<<20, imp bits}
__device__ int2  g_im   [NNZ_IM];    // {col, val bits}
__device__ int2  g_icm  [NNZ_ICM];   // {col | cls<<16, val bits}

// ---------------- side-stream prep ----------------
__global__ void convert_kernel(const float2* __restrict__ e2, __half2* __restrict__ eh,
                               const float* __restrict__ rel) {
    int i = blockIdx.x * blockDim.x + threadIdx.x;
    if (i < CONV_N) eh[i] = __float22half2_rn(e2[i]);
    if (i < D) {
        float s = 0.f;
#pragma unroll
        for (int r = 0; r < N_REL; r++) s += rel[r * D + i];
        g_relsum[i] = s;
    }
}

// ---------------- build ----------------
__global__ void zero_counts_kernel() {
    int i = blockIdx.x * blockDim.x + threadIdx.x;
    if (i < N_SEGS) g_counts[i] = 0;
}

__global__ void count_kernel(const int* __restrict__ head,
                             const int* __restrict__ im_rows,
                             const int* __restrict__ icm_rows) {
    int i = blockIdx.x * blockDim.x + threadIdx.x;
    if (i < N_EDGES) {
        atomicAdd(&g_counts[head[i]], 1);
    } else if (i < N_EDGES + NNZ_IM) {
        atomicAdd(&g_counts[IM_SEG0 + im_rows[i - N_EDGES]], 1);
    } else if (i < TOT_NNZ) {
        atomicAdd(&g_counts[ICM_SEG0 + icm_rows[i - N_EDGES - NNZ_IM]], 1);
    }
}

__global__ void scanA_kernel() {
    __shared__ int s[SCAN_TILE];
    int idx = blockIdx.x * SCAN_TILE + threadIdx.x;
    s[threadIdx.x] = (idx < N_SEGS) ? g_counts[idx] : 0;
    __syncthreads();
    for (int off = SCAN_TILE / 2; off > 0; off >>= 1) {
        if (threadIdx.x < off) s[threadIdx.x] += s[threadIdx.x + off];
        __syncthreads();
    }
    if (threadIdx.x == 0) g_tilesum[blockIdx.x] = s[0];
}

__global__ void scanB_kernel() {
    __shared__ int s[256];
    int t = threadIdx.x;
    int v = (t < N_TILES) ? g_tilesum[t] : 0;
    s[t] = v;
    __syncthreads();
    for (int off = 1; off < 256; off <<= 1) {
        int w = (t >= off) ? s[t - off] : 0;
        __syncthreads();
        s[t] += w;
        __syncthreads();
    }
    if (t < N_TILES) g_tilebase[t] = s[t] - v;
}

__global__ void scanC_kernel() {
    __shared__ int s[SCAN_TILE];
    int t = threadIdx.x;
    int idx = blockIdx.x * SCAN_TILE + t;
    int v = (idx < N_SEGS) ? g_counts[idx] : 0;
    s[t] = v;
    __syncthreads();
    for (int off = 1; off < SCAN_TILE; off <<= 1) {
        int w = (t >= off) ? s[t - off] : 0;
        __syncthreads();
        s[t] += w;
        __syncthreads();
    }
    if (idx < N_SEGS) {
        int excl = g_tilebase[blockIdx.x] + s[t] - v;
        g_offsets[idx] = excl;
        g_cursor[idx]  = excl;
    }
}

__global__ void fill_edge_kernel(const int* __restrict__ head, const int* __restrict__ tail,
                                 const int* __restrict__ etype, const float* __restrict__ eimp) {
    int i = blockIdx.x * blockDim.x + threadIdx.x;
    if (i < N_EDGES) {
        int h = head[i];
        int pos = atomicAdd(&g_cursor[h], 1);
        g_edge[pos] = make_int2(tail[i] | (etype[i] << 20), __float_as_int(eimp[i]));
    }
}

__global__ void fill_imicm_kernel(const int* __restrict__ im_rows, const int* __restrict__ im_cols,
                                  const float* __restrict__ im_vals,
                                  const int* __restrict__ icm_rows, const int* __restrict__ icm_cols,
                                  const int* __restrict__ icm_cls, const float* __restrict__ icm_vals) {
    int i = blockIdx.x * blockDim.x + threadIdx.x;
    if (i < NNZ_IM) {
        int r = im_rows[i];
        int pos = atomicAdd(&g_cursor[IM_SEG0 + r], 1) - IM_BASE;
        g_im[pos] = make_int2(im_cols[i], __float_as_int(im_vals[i]));
    } else if (i < NNZ_IMICM) {
        int j = i - NNZ_IM;
        int r = icm_rows[j];
        int pos = atomicAdd(&g_cursor[ICM_SEG0 + r], 1) - ICM_BASE;
        g_icm[pos] = make_int2(icm_cols[j] | (icm_cls[j] << 16), __float_as_int(icm_vals[j]));
    }
}

// ---------------- hop-0 att+ucls (fp32 inputs) ----------------
__global__ void attucls0_kernel(const float* __restrict__ e, const float* __restrict__ u,
                                const float* __restrict__ rel, const float* __restrict__ w) {
    __shared__ float s_rel[N_REL * D];
    __shared__ float s_w[N_CLUSTERS * D];
    for (int i = threadIdx.x; i < N_REL * D; i += blockDim.x) s_rel[i] = rel[i];
    for (int i = threadIdx.x; i < N_CLUSTERS * D; i += blockDim.x) s_w[i] = w[i];
    __syncthreads();
    int i = blockIdx.x * blockDim.x + threadIdx.x;
    if (i < N_ENTITIES) {
        const float4* row = (const float4*)(e + (size_t)i * D);
        float acc[N_REL];
#pragma unroll
        for (int r = 0; r < N_REL; r++) acc[r] = 0.f;
#pragma unroll
        for (int k = 0; k < D / 4; k++) {
            float4 ev = row[k];
#pragma unroll
            for (int r = 0; r < N_REL; r++) {
                float4 rv = ((const float4*)(s_rel + r * D))[k];
                acc[r] += ev.x * rv.x + ev.y * rv.y + ev.z * rv.z + ev.w * rv.w;
            }
        }
        float mx = acc[0];
#pragma unroll
        for (int r = 1; r < N_REL; r++) mx = fmaxf(mx, acc[r]);
        float sum = 0.f;
#pragma unroll
        for (int r = 0; r < N_REL; r++) { acc[r] = expf(acc[r] - mx); sum += acc[r]; }
        float inv = 1.f / sum;
#pragma unroll
        for (int r = 0; r < N_REL; r++) g_att[(size_t)i * N_REL + r] = acc[r] * inv;
    } else if (i < N_ENTITIES + N_USERS) {
        int uidx = i - N_ENTITIES;
        const float4* row = (const float4*)(u + (size_t)uidx * D);
        float acc[N_CLUSTERS] = {0.f, 0.f, 0.f, 0.f};
#pragma unroll
        for (int k = 0; k < D / 4; k++) {
            float4 uv = row[k];
#pragma unroll
            for (int c = 0; c < N_CLUSTERS; c++) {
                float4 wv = ((const float4*)(s_w + c * D))[k];
                acc[c] += uv.x * wv.x + uv.y * wv.y + uv.z * wv.z + uv.w * wv.w;
            }
        }
        float mx = fmaxf(fmaxf(acc[0], acc[1]), fmaxf(acc[2], acc[3]));
        float sum = 0.f;
#pragma unroll
        for (int c = 0; c < N_CLUSTERS; c++) { acc[c] = expf(acc[c] - mx); sum += acc[c]; }
        float inv = 1.f / sum;
#pragma unroll
        for (int c = 0; c < N_CLUSTERS; c++) g_ucls[(size_t)uidx * N_CLUSTERS + c] = acc[c] * inv;
    }
}

// ---------------- hop-1 att (entity, fp16 source) ----------------
__global__ void att_e_kernel(const __half2* __restrict__ eh, const float* __restrict__ rel) {
    __shared__ float s_rel[N_REL * D];
    for (int i = threadIdx.x; i < N_REL * D; i += blockDim.x) s_rel[i] = rel[i];
    __syncthreads();
    int i = blockIdx.x * blockDim.x + threadIdx.x;
    if (i >= N_ENTITIES) return;
    const __half2* row = eh + (size_t)i * (D / 2);
    float acc[N_REL];
#pragma unroll
    for (int r = 0; r < N_REL; r++) acc[r] = 0.f;
#pragma unroll
    for (int k = 0; k < D / 2; k++) {
        float2 ev = __half22float2(row[k]);
#pragma unroll
        for (int r = 0; r < N_REL; r++) {
            float2 rv = ((const float2*)(s_rel + r * D))[k];
            acc[r] += ev.x * rv.x + ev.y * rv.y;
        }
    }
    float mx = acc[0];
#pragma unroll
    for (int r = 1; r < N_REL; r++) mx = fmaxf(mx, acc[r]);
    float sum = 0.f;
#pragma unroll
    for (int r = 0; r < N_REL; r++) { acc[r] = expf(acc[r] - mx); sum += acc[r]; }
    float inv = 1.f / sum;
#pragma unroll
    for (int r = 0; r < N_REL; r++) g_att[(size_t)i * N_REL + r] = acc[r] * inv;
}

// ---------------- hop-1 ucls ----------------
__global__ void ucls_u_kernel(const float* __restrict__ u, const float* __restrict__ w) {
    __shared__ float s_w[N_CLUSTERS * D];
    for (int i = threadIdx.x; i < N_CLUSTERS * D; i += blockDim.x) s_w[i] = w[i];
    __syncthreads();
    int i = blockIdx.x * blockDim.x + threadIdx.x;
    if (i >= N_USERS) return;
    const float4* row = (const float4*)(u + (size_t)i * D);
    float acc[N_CLUSTERS] = {0.f, 0.f, 0.f, 0.f};
#pragma unroll
    for (int k = 0; k < D / 4; k++) {
        float4 uv = row[k];
#pragma unroll
        for (int c = 0; c < N_CLUSTERS; c++) {
            float4 wv = ((const float4*)(s_w + c * D))[k];
            acc[c] += uv.x * wv.x + uv.y * wv.y + uv.z * wv.z + uv.w * wv.w;
        }
    }
    float mx = fmaxf(fmaxf(acc[0], acc[1]), fmaxf(acc[2], acc[3]));
    float sum = 0.f;
#pragma unroll
    for (int c = 0; c < N_CLUSTERS; c++) { acc[c] = expf(acc[c] - mx); sum += acc[c]; }
    float inv = 1.f / sum;
#pragma unroll
    for (int c = 0; c < N_CLUSTERS; c++) g_ucls[(size_t)i * N_CLUSTERS + c] = acc[c] * inv;
}

// ---------------- entity gather (R11 loop, occupancy-boosted) ----------------
template <bool HOP0, bool LAST>
__global__ void __launch_bounds__(256, 5)
ent_gather_kernel(const __half2* __restrict__ eh,
                  const float* __restrict__ rel,
                  __half2* __restrict__ eh_out,
                  const float2* __restrict__ base_ent, float2* __restrict__ res_ent) {
    __shared__ float2 s_rel[N_REL * 32];
    for (int i = threadIdx.x; i < N_REL * 32; i += blockDim.x)
        s_rel[i] = ((const float2*)rel)[i];
    __syncthreads();

    int warp = (blockIdx.x * blockDim.x + threadIdx.x) >> 5;
    int lane = threadIdx.x & 31;
    if (warp >= N_ENTITIES) return;
    float2 acc = make_float2(0.f, 0.f);

    int start = g_offsets[warp];
    int cnt   = g_counts[warp];
    const int2* ep = g_edge + start;
    const float* attrow = g_att + (size_t)warp * N_REL;
    int j = 0;
    for (; j + 8 <= cnt; j += 8) {
        int2 a[8];
#pragma unroll
        for (int q = 0; q < 8; q++) a[q] = ep[j + q];
        float w[8];
        int t[8], r[8];
#pragma unroll
        for (int q = 0; q < 8; q++) {
            t[q] = a[q].x & 0xFFFFF;
            r[q] = a[q].x >> 20;
            w[q] = __int_as_float(a[q].y) * attrow[r[q]];
        }
        float2 v[8];
#pragma unroll
        for (int q = 0; q < 8; q++) v[q] = __half22float2(eh[(size_t)t[q] * 32 + lane]);
#pragma unroll
        for (int q = 0; q < 8; q++) {
            float2 qr = s_rel[r[q] * 32 + lane];
            acc.x += w[q] * v[q].x * qr.x;
            acc.y += w[q] * v[q].y * qr.y;
        }
    }
    for (; j < cnt; j++) {
        int2 a = ep[j];
        int t = a.x & 0xFFFFF, r = a.x >> 20;
        float wv = __int_as_float(a.y) * attrow[r];
        float2 v = __half22float2(eh[(size_t)t * 32 + lane]);
        float2 q = s_rel[r * 32 + lane];
        acc.x += wv * v.x * q.x;
        acc.y += wv * v.y * q.y;
    }
    float ss = acc.x * acc.x + acc.y * acc.y;
#pragma unroll
    for (int o = 16; o; o >>= 1) ss += __shfl_xor_sync(0xffffffffu, ss, o);
    float inv = 1.f / fmaxf(sqrtf(ss), 1e-12f);
    float2 o2 = make_float2(acc.x * inv, acc.y * inv);
    if (!LAST) eh_out[(size_t)warp * 32 + lane] = __float22half2_rn(o2);
    float2 cur = HOP0 ? base_ent[(size_t)warp * 32 + lane]
                      : res_ent[(size_t)warp * 32 + lane];
    cur.x += o2.x; cur.y += o2.y;
    res_ent[(size_t)warp * 32 + lane] = cur;
}

// ---------------- user gather (R11 loop, occupancy-boosted) ----------------
template <bool HOP0, bool LAST>
__global__ void __launch_bounds__(256, 5)
usr_gather_kernel(const __half2* __restrict__ eh,
                  float* __restrict__ u_out,
                  const float2* __restrict__ base_usr, float2* __restrict__ res_usr) {
    __shared__ float2 s_rs[32];
    if (threadIdx.x < 32) s_rs[threadIdx.x] = ((const float2*)g_relsum)[threadIdx.x];
    __syncthreads();

    int warp = (blockIdx.x * blockDim.x + threadIdx.x) >> 5;
    int lane = threadIdx.x & 31;
    if (warp >= N_USERS) return;
    int uidx = warp;
    float2 rs = s_rs[lane];
    const float* ucrow = g_ucls + (size_t)uidx * N_CLUSTERS;
    float2 acc = make_float2(0.f, 0.f);

    // im segment
    {
        int start = g_offsets[IM_SEG0 + uidx] - IM_BASE;
        int cnt   = g_counts[IM_SEG0 + uidx];
        const int2* ep = g_im + start;
        int j = 0;
        for (; j + 8 <= cnt; j += 8) {
            int2 a[8];
#pragma unroll
            for (int q = 0; q < 8; q++) a[q] = ep[j + q];
            float2 v[8];
#pragma unroll
            for (int q = 0; q < 8; q++) v[q] = __half22float2(eh[(size_t)a[q].x * 32 + lane]);
#pragma unroll
            for (int q = 0; q < 8; q++) {
                float w = __int_as_float(a[q].y);
                acc.x += w * v[q].x;
                acc.y += w * v[q].y;
            }
        }
        for (; j < cnt; j++) {
            int2 a = ep[j];
            float2 v = __half22float2(eh[(size_t)a.x * 32 + lane]);
            float w = __int_as_float(a.y);
            acc.x += w * v.x;
            acc.y += w * v.y;
        }
    }
    // icm segment (fused dw einsum)
    float2 acc2 = make_float2(0.f, 0.f);
    {
        int start = g_offsets[ICM_SEG0 + uidx] - ICM_BASE;
        int cnt   = g_counts[ICM_SEG0 + uidx];
        const int2* ep = g_icm + start;
        int j = 0;
        for (; j + 8 <= cnt; j += 8) {
            int2 a[8];
#pragma unroll
            for (int q = 0; q < 8; q++) a[q] = ep[j + q];
            float w[8];
#pragma unroll
            for (int q = 0; q < 8; q++)
                w[q] = __int_as_float(a[q].y) * ucrow[a[q].x >> 16];
            float2 v[8];
#pragma unroll
            for (int q = 0; q < 8; q++)
                v[q] = __half22float2(eh[(size_t)(a[q].x & 0xFFFF) * 32 + lane]);
#pragma unroll
            for (int q = 0; q < 8; q++) {
                acc2.x += w[q] * v[q].x;
                acc2.y += w[q] * v[q].y;
            }
        }
        for (; j < cnt; j++) {
            int2 a = ep[j];
            int c = a.x & 0xFFFF, k = a.x >> 16;
            float w = __int_as_float(a.y) * ucrow[k];
            float2 v = __half22float2(eh[(size_t)c * 32 + lane]);
            acc2.x += w * v.x;
            acc2.y += w * v.y;
        }
    }
    acc.x += acc2.x * rs.x;
    acc.y += acc2.y * rs.y;

    float ss = acc.x * acc.x + acc.y * acc.y;
#pragma unroll
    for (int o = 16; o; o >>= 1) ss += __shfl_xor_sync(0xffffffffu, ss, o);
    float inv = 1.f / fmaxf(sqrtf(ss), 1e-12f);
    float2 o2 = make_float2(acc.x * inv, acc.y * inv);
    if (!LAST) ((float2*)(u_out + (size_t)uidx * D))[lane] = o2;
    float2 cur = HOP0 ? base_usr[(size_t)uidx * 32 + lane]
                      : res_usr[(size_t)uidx * 32 + lane];
    cur.x += o2.x; cur.y += o2.y;
    res_usr[(size_t)uidx * 32 + lane] = cur;
}

// ---------------- cor loss ----------------
__global__ void cor_kernel(const float* __restrict__ dw, float* __restrict__ out) {
    float nt[N_FACTORS][N_REL];
#pragma unroll
    for (int c = 0; c < N_FACTORS; c++) {
        float ss = 0.f;
#pragma unroll
        for (int k = 0; k < N_REL; k++) { float x = dw[c * N_REL + k]; ss += x * x; }
        float inv = 1.f / fmaxf(sqrtf(ss), 1e-12f);
#pragma unroll
        for (int k = 0; k < N_REL; k++) nt[c][k] = dw[c * N_REL + k] * inv;
    }
    float loss = 0.f;
#pragma unroll
    for (int i = 0; i < N_FACTORS; i++) {
        float ssum = 0.f, diag = 0.f;
#pragma unroll
        for (int j = 0; j < N_FACTORS; j++) {
            float dot = 0.f;
#pragma unroll
            for (int k = 0; k < N_REL; k++) dot += nt[i][k] * nt[j][k];
            float s = expf(dot / TMP);
            ssum += s;
            if (i == j) diag = s;
        }
        loss -= logf(diag / ssum);
    }
    out[0] = loss;
}

// ---------------- launch ----------------
extern "C" void kernel_launch(void* const* d_in, const int* in_sizes, int n_in,
                              void* d_out, int out_size) {
    const float* user_emb     = (const float*)d_in[0];
    const float* entity_emb   = (const float*)d_in[1];
    const float* relation_emb = (const float*)d_in[3];
    const float* disen        = (const float*)d_in[4];
    const float* usr_cls_w    = (const float*)d_in[5];
    const float* edge_imp     = (const float*)d_in[6];
    const float* im_vals      = (const float*)d_in[7];
    const float* icm_vals     = (const float*)d_in[8];
    const int*   edge_index   = (const int*)d_in[9];
    const int*   edge_type    = (const int*)d_in[10];
    const int*   im_rows      = (const int*)d_in[11];
    const int*   im_cols      = (const int*)d_in[12];
    const int*   icm_cls      = (const int*)d_in[13];
    const int*   icm_rows     = (const int*)d_in[14];
    const int*   icm_cols     = (const int*)d_in[15];

    float* out     = (float*)d_out;
    float* out_ent = out;
    float* out_usr = out + (size_t)N_ENTITIES * D;
    float* out_cor = out + (size_t)N_ENTITIES * D + (size_t)N_USERS * D;

    __half *p_ehA, *p_ehB;
    float *p_u;
    cudaGetSymbolAddress((void**)&p_ehA, g_ehA);
    cudaGetSymbolAddress((void**)&p_ehB, g_ehB);
    cudaGetSymbolAddress((void**)&p_u, g_u);

    static cudaStream_t s1 = nullptr, s2 = nullptr;
    static cudaEvent_t ev_fork = nullptr, ev_prep = nullptr, ev_scan = nullptr,
                       ev_ent0 = nullptr, ev_usr = nullptr;
    if (s1 == nullptr) {
        cudaStreamCreateWithFlags(&s1, cudaStreamNonBlocking);
        cudaStreamCreateWithFlags(&s2, cudaStreamNonBlocking);
        cudaEventCreateWithFlags(&ev_fork, cudaEventDisableTiming);
        cudaEventCreateWithFlags(&ev_prep, cudaEventDisableTiming);
        cudaEventCreateWithFlags(&ev_scan, cudaEventDisableTiming);
        cudaEventCreateWithFlags(&ev_ent0, cudaEventDisableTiming);
        cudaEventCreateWithFlags(&ev_usr, cudaEventDisableTiming);
    }

    const int TPB = 256;
    unsigned ablocks  = (N_ENTITIES + N_USERS + TPB - 1) / TPB;
    unsigned eblocks  = (N_ENTITIES + TPB - 1) / TPB;
    unsigned ublocks  = (N_USERS + TPB - 1) / TPB;
    unsigned egblocks = (unsigned)(((long long)N_ENTITIES * 32 + TPB - 1) / TPB);
    unsigned ugblocks = (unsigned)(((long long)N_USERS * 32 + TPB - 1) / TPB);

    // ---- fork s1: convert+relsum, hop-0 att/ucls, cor ----
    cudaEventRecord(ev_fork, 0);
    cudaStreamWaitEvent(s1, ev_fork, 0);
    cudaStreamWaitEvent(s2, ev_fork, 0);
    convert_kernel<<<(CONV_N + TPB - 1) / TPB, TPB, 0, s1>>>(
        (const float2*)entity_emb, (__half2*)p_ehA, relation_emb);
    attucls0_kernel<<<ablocks, TPB, 0, s1>>>(entity_emb, user_emb, relation_emb, usr_cls_w);
    cor_kernel<<<1, 1, 0, s1>>>(disen, out_cor);
    cudaEventRecord(ev_prep, s1);

    // ---- main: count + scan ----
    zero_counts_kernel<<<(N_SEGS + TPB - 1) / TPB, TPB>>>();
    count_kernel<<<(TOT_NNZ + TPB - 1) / TPB, TPB>>>(edge_index, im_rows, icm_rows);
    scanA_kernel<<<N_TILES, SCAN_TILE>>>();
    scanB_kernel<<<1, 256>>>();
    scanC_kernel<<<N_TILES, SCAN_TILE>>>();
    cudaEventRecord(ev_scan, 0);

    // ---- s2: im/icm fill + user chain ----
    cudaStreamWaitEvent(s2, ev_scan, 0);
    fill_imicm_kernel<<<(NNZ_IMICM + TPB - 1) / TPB, TPB, 0, s2>>>(
        im_rows, im_cols, im_vals, icm_rows, icm_cols, icm_cls, icm_vals);
    cudaStreamWaitEvent(s2, ev_prep, 0);
    usr_gather_kernel<true, false><<<ugblocks, TPB, 0, s2>>>(
        (const __half2*)p_ehA, p_u, (const float2*)user_emb, (float2*)out_usr);
    ucls_u_kernel<<<ublocks, TPB, 0, s2>>>(p_u, usr_cls_w);

    // ---- main: edge fill + entity chain ----
    fill_edge_kernel<<<(N_EDGES + TPB - 1) / TPB, TPB>>>(
        edge_index, edge_index + N_EDGES, edge_type, edge_imp);
    cudaStreamWaitEvent(0, ev_prep, 0);
    ent_gather_kernel<true, false><<<egblocks, TPB>>>(
        (const __half2*)p_ehA, relation_emb, (__half2*)p_ehB,
        (const float2*)entity_emb, (float2*)out_ent);
    cudaEventRecord(ev_ent0, 0);

    // ---- s2: hop-1 user gather (needs ehB + ucls1) ----
    cudaStreamWaitEvent(s2, ev_ent0, 0);
    usr_gather_kernel<false, true><<<ugblocks, TPB, 0, s2>>>(
        (const __half2*)p_ehB, p_u, nullptr, (float2*)out_usr);
    cudaEventRecord(ev_usr, s2);

    // ---- main: hop-1 entity att + gather ----
    att_e_kernel<<<eblocks, TPB>>>((const __half2*)p_ehB, relation_emb);
    ent_gather_kernel<false, true><<<egblocks, TPB>>>(
        (const __half2*)p_ehB, relation_emb, (__half2*)p_ehA,
        nullptr, (float2*)out_ent);

    // ---- join all ----
    cudaStreamWaitEvent(0, ev_usr, 0);
}

// round 15
// speedup vs baseline: 1.2685x; 1.0238x over previous
#include <cuda_runtime.h>
#include <cuda_fp16.h>
#include <cstdint>

#define N_ENTITIES 100000
#define N_USERS    50000
#define N_ITEMS    30000
#define D          64
#define N_REL      16
#define N_FACTORS  4
#define N_CLUSTERS 4
#define N_EDGES    1500000
#define NNZ_IM     1000000
#define NNZ_ICM    1000000
#define N_HOPS     2
#define TMP        0.2f

#define N_SEGS     (N_ENTITIES + N_USERS + N_USERS)   // 200000
#define IM_SEG0    N_ENTITIES
#define ICM_SEG0   (N_ENTITIES + N_USERS)
#define IM_BASE    N_EDGES
#define ICM_BASE   (N_EDGES + NNZ_IM)
#define TOT_NNZ    (N_EDGES + NNZ_IM + NNZ_ICM)       // 3.5M
#define NNZ_IMICM  (NNZ_IM + NNZ_ICM)                 // 2M

#define SCAN_TILE  1024
#define N_TILES    ((N_SEGS + SCAN_TILE - 1) / SCAN_TILE)   // 196

#define CONV_N     (N_ENTITIES * D / 2)

// ---------------- scratch ----------------
__device__ float  g_att [N_ENTITIES * N_REL];
__device__ float  g_ucls[N_USERS * N_CLUSTERS];
__device__ __half g_ehA [N_ENTITIES * D];
__device__ __half g_ehB [N_ENTITIES * D];
__device__ float  g_u   [N_USERS * D];
__device__ float  g_relsum[D];

__device__ int   g_counts  [N_SEGS];
__device__ int   g_offsets [N_SEGS];
__device__ int   g_cursor  [N_SEGS];
__device__ int   g_tilesum [N_TILES];
__device__ int   g_tilebase[N_TILES];
__device__ int2  g_edge [N_EDGES];   // {tail | etype<<20, imp bits}
__device__ int2  g_im   [NNZ_IM];    // {col, val bits}
__device__ int2  g_icm  [NNZ_ICM];   // {col | cls<<16, val bits}

// ---------------- side-stream prep ----------------
__global__ void convert_kernel(const float2* __restrict__ e2, __half2* __restrict__ eh,
                               const float* __restrict__ rel) {
    int i = blockIdx.x * blockDim.x + threadIdx.x;
    if (i < CONV_N) eh[i] = __float22half2_rn(e2[i]);
    if (i < D) {
        float s = 0.f;
#pragma unroll
        for (int r = 0; r < N_REL; r++) s += rel[r * D + i];
        g_relsum[i] = s;
    }
}

// ---------------- build ----------------
__global__ void zero_counts_kernel() {
    int i = blockIdx.x * blockDim.x + threadIdx.x;
    if (i < N_SEGS) g_counts[i] = 0;
}

__global__ void count_kernel(const int* __restrict__ head,
                             const int* __restrict__ im_rows,
                             const int* __restrict__ icm_rows) {
    int i = blockIdx.x * blockDim.x + threadIdx.x;
    if (i < N_EDGES) {
        atomicAdd(&g_counts[head[i]], 1);
    } else if (i < N_EDGES + NNZ_IM) {
        atomicAdd(&g_counts[IM_SEG0 + im_rows[i - N_EDGES]], 1);
    } else if (i < TOT_NNZ) {
        atomicAdd(&g_counts[ICM_SEG0 + icm_rows[i - N_EDGES - NNZ_IM]], 1);
    }
}

__global__ void scanA_kernel() {
    __shared__ int s[SCAN_TILE];
    int idx = blockIdx.x * SCAN_TILE + threadIdx.x;
    s[threadIdx.x] = (idx < N_SEGS) ? g_counts[idx] : 0;
    __syncthreads();
    for (int off = SCAN_TILE / 2; off > 0; off >>= 1) {
        if (threadIdx.x < off) s[threadIdx.x] += s[threadIdx.x + off];
        __syncthreads();
    }
    if (threadIdx.x == 0) g_tilesum[blockIdx.x] = s[0];
}

__global__ void scanB_kernel() {
    __shared__ int s[256];
    int t = threadIdx.x;
    int v = (t < N_TILES) ? g_tilesum[t] : 0;
    s[t] = v;
    __syncthreads();
    for (int off = 1; off < 256; off <<= 1) {
        int w = (t >= off) ? s[t - off] : 0;
        __syncthreads();
        s[t] += w;
        __syncthreads();
    }
    if (t < N_TILES) g_tilebase[t] = s[t] - v;
}

__global__ void scanC_kernel() {
    __shared__ int s[SCAN_TILE];
    int t = threadIdx.x;
    int idx = blockIdx.x * SCAN_TILE + t;
    int v = (idx < N_SEGS) ? g_counts[idx] : 0;
    s[t] = v;
    __syncthreads();
    for (int off = 1; off < SCAN_TILE; off <<= 1) {
        int w = (t >= off) ? s[t - off] : 0;
        __syncthreads();
        s[t] += w;
        __syncthreads();
    }
    if (idx < N_SEGS) {
        int excl = g_tilebase[blockIdx.x] + s[t] - v;
        g_offsets[idx] = excl;
        g_cursor[idx]  = excl;
    }
}

__global__ void fill_edge_kernel(const int* __restrict__ head, const int* __restrict__ tail,
                                 const int* __restrict__ etype, const float* __restrict__ eimp) {
    int i = blockIdx.x * blockDim.x + threadIdx.x;
    if (i < N_EDGES) {
        int h = head[i];
        int pos = atomicAdd(&g_cursor[h], 1);
        g_edge[pos] = make_int2(tail[i] | (etype[i] << 20), __float_as_int(eimp[i]));
    }
}

__global__ void fill_imicm_kernel(const int* __restrict__ im_rows, const int* __restrict__ im_cols,
                                  const float* __restrict__ im_vals,
                                  const int* __restrict__ icm_rows, const int* __restrict__ icm_cols,
                                  const int* __restrict__ icm_cls, const float* __restrict__ icm_vals) {
    int i = blockIdx.x * blockDim.x + threadIdx.x;
    if (i < NNZ_IM) {
        int r = im_rows[i];
        int pos = atomicAdd(&g_cursor[IM_SEG0 + r], 1) - IM_BASE;
        g_im[pos] = make_int2(im_cols[i], __float_as_int(im_vals[i]));
    } else if (i < NNZ_IMICM) {
        int j = i - NNZ_IM;
        int r = icm_rows[j];
        int pos = atomicAdd(&g_cursor[ICM_SEG0 + r], 1) - ICM_BASE;
        g_icm[pos] = make_int2(icm_cols[j] | (icm_cls[j] << 16), __float_as_int(icm_vals[j]));
    }
}

// ---------------- hop-0 att+ucls (fp32 inputs) ----------------
__global__ void attucls0_kernel(const float* __restrict__ e, const float* __restrict__ u,
                                const float* __restrict__ rel, const float* __restrict__ w) {
    __shared__ float s_rel[N_REL * D];
    __shared__ float s_w[N_CLUSTERS * D];
    for (int i = threadIdx.x; i < N_REL * D; i += blockDim.x) s_rel[i] = rel[i];
    for (int i = threadIdx.x; i < N_CLUSTERS * D; i += blockDim.x) s_w[i] = w[i];
    __syncthreads();
    int i = blockIdx.x * blockDim.x + threadIdx.x;
    if (i < N_ENTITIES) {
        const float4* row = (const float4*)(e + (size_t)i * D);
        float acc[N_REL];
#pragma unroll
        for (int r = 0; r < N_REL; r++) acc[r] = 0.f;
#pragma unroll
        for (int k = 0; k < D / 4; k++) {
            float4 ev = row[k];
#pragma unroll
            for (int r = 0; r < N_REL; r++) {
                float4 rv = ((const float4*)(s_rel + r * D))[k];
                acc[r] += ev.x * rv.x + ev.y * rv.y + ev.z * rv.z + ev.w * rv.w;
            }
        }
        float mx = acc[0];
#pragma unroll
        for (int r = 1; r < N_REL; r++) mx = fmaxf(mx, acc[r]);
        float sum = 0.f;
#pragma unroll
        for (int r = 0; r < N_REL; r++) { acc[r] = expf(acc[r] - mx); sum += acc[r]; }
        float inv = 1.f / sum;
#pragma unroll
        for (int r = 0; r < N_REL; r++) g_att[(size_t)i * N_REL + r] = acc[r] * inv;
    } else if (i < N_ENTITIES + N_USERS) {
        int uidx = i - N_ENTITIES;
        const float4* row = (const float4*)(u + (size_t)uidx * D);
        float acc[N_CLUSTERS] = {0.f, 0.f, 0.f, 0.f};
#pragma unroll
        for (int k = 0; k < D / 4; k++) {
            float4 uv = row[k];
#pragma unroll
            for (int c = 0; c < N_CLUSTERS; c++) {
                float4 wv = ((const float4*)(s_w + c * D))[k];
                acc[c] += uv.x * wv.x + uv.y * wv.y + uv.z * wv.z + uv.w * wv.w;
            }
        }
        float mx = fmaxf(fmaxf(acc[0], acc[1]), fmaxf(acc[2], acc[3]));
        float sum = 0.f;
#pragma unroll
        for (int c = 0; c < N_CLUSTERS; c++) { acc[c] = expf(acc[c] - mx); sum += acc[c]; }
        float inv = 1.f / sum;
#pragma unroll
        for (int c = 0; c < N_CLUSTERS; c++) g_ucls[(size_t)uidx * N_CLUSTERS + c] = acc[c] * inv;
    }
}

// ---------------- hop-1 att (entity, fp16 source) ----------------
__global__ void att_e_kernel(const __half2* __restrict__ eh, const float* __restrict__ rel) {
    __shared__ float s_rel[N_REL * D];
    for (int i = threadIdx.x; i < N_REL * D; i += blockDim.x) s_rel[i] = rel[i];
    __syncthreads();
    int i = blockIdx.x * blockDim.x + threadIdx.x;
    if (i >= N_ENTITIES) return;
    const __half2* row = eh + (size_t)i * (D / 2);
    float acc[N_REL];
#pragma unroll
    for (int r = 0; r < N_REL; r++) acc[r] = 0.f;
#pragma unroll
    for (int k = 0; k < D / 2; k++) {
        float2 ev = __half22float2(row[k]);
#pragma unroll
        for (int r = 0; r < N_REL; r++) {
            float2 rv = ((const float2*)(s_rel + r * D))[k];
            acc[r] += ev.x * rv.x + ev.y * rv.y;
        }
    }
    float mx = acc[0];
#pragma unroll
    for (int r = 1; r < N_REL; r++) mx = fmaxf(mx, acc[r]);
    float sum = 0.f;
#pragma unroll
    for (int r = 0; r < N_REL; r++) { acc[r] = expf(acc[r] - mx); sum += acc[r]; }
    float inv = 1.f / sum;
#pragma unroll
    for (int r = 0; r < N_REL; r++) g_att[(size_t)i * N_REL + r] = acc[r] * inv;
}

// ---------------- hop-1 ucls ----------------
__global__ void ucls_u_kernel(const float* __restrict__ u, const float* __restrict__ w) {
    __shared__ float s_w[N_CLUSTERS * D];
    for (int i = threadIdx.x; i < N_CLUSTERS * D; i += blockDim.x) s_w[i] = w[i];
    __syncthreads();
    int i = blockIdx.x * blockDim.x + threadIdx.x;
    if (i >= N_USERS) return;
    const float4* row = (const float4*)(u + (size_t)i * D);
    float acc[N_CLUSTERS] = {0.f, 0.f, 0.f, 0.f};
#pragma unroll
    for (int k = 0; k < D / 4; k++) {
        float4 uv = row[k];
#pragma unroll
        for (int c = 0; c < N_CLUSTERS; c++) {
            float4 wv = ((const float4*)(s_w + c * D))[k];
            acc[c] += uv.x * wv.x + uv.y * wv.y + uv.z * wv.z + uv.w * wv.w;
        }
    }
    float mx = fmaxf(fmaxf(acc[0], acc[1]), fmaxf(acc[2], acc[3]));
    float sum = 0.f;
#pragma unroll
    for (int c = 0; c < N_CLUSTERS; c++) { acc[c] = expf(acc[c] - mx); sum += acc[c]; }
    float inv = 1.f / sum;
#pragma unroll
    for (int c = 0; c < N_CLUSTERS; c++) g_ucls[(size_t)i * N_CLUSTERS + c] = acc[c] * inv;
}

// ---------------- entity gather (8-deep unroll + rolled remainder) ----------------
template <bool HOP0, bool LAST>
__global__ void __launch_bounds__(256)
ent_gather_kernel(const __half2* __restrict__ eh,
                  const float* __restrict__ rel,
                  __half2* __restrict__ eh_out,
                  const float2* __restrict__ base_ent, float2* __restrict__ res_ent) {
    __shared__ float2 s_rel[N_REL * 32];
    for (int i = threadIdx.x; i < N_REL * 32; i += blockDim.x)
        s_rel[i] = ((const float2*)rel)[i];
    __syncthreads();

    int warp = (blockIdx.x * blockDim.x + threadIdx.x) >> 5;
    int lane = threadIdx.x & 31;
    if (warp >= N_ENTITIES) return;
    float2 acc = make_float2(0.f, 0.f);

    int start = g_offsets[warp];
    int cnt   = g_counts[warp];
    const int2* ep = g_edge + start;
    const float* attrow = g_att + (size_t)warp * N_REL;
    int j = 0;
    for (; j + 8 <= cnt; j += 8) {
        int2 a[8];
#pragma unroll
        for (int q = 0; q < 8; q++) a[q] = ep[j + q];
        float w[8];
        int t[8], r[8];
#pragma unroll
        for (int q = 0; q < 8; q++) {
            t[q] = a[q].x & 0xFFFFF;
            r[q] = a[q].x >> 20;
            w[q] = __int_as_float(a[q].y) * attrow[r[q]];
        }
        float2 v[8];
#pragma unroll
        for (int q = 0; q < 8; q++) v[q] = __half22float2(eh[(size_t)t[q] * 32 + lane]);
#pragma unroll
        for (int q = 0; q < 8; q++) {
            float2 qr = s_rel[r[q] * 32 + lane];
            acc.x += w[q] * v[q].x * qr.x;
            acc.y += w[q] * v[q].y * qr.y;
        }
    }
    for (; j < cnt; j++) {
        int2 a = ep[j];
        int t = a.x & 0xFFFFF, r = a.x >> 20;
        float wv = __int_as_float(a.y) * attrow[r];
        float2 v = __half22float2(eh[(size_t)t * 32 + lane]);
        float2 q = s_rel[r * 32 + lane];
        acc.x += wv * v.x * q.x;
        acc.y += wv * v.y * q.y;
    }
    float ss = acc.x * acc.x + acc.y * acc.y;
#pragma unroll
    for (int o = 16; o; o >>= 1) ss += __shfl_xor_sync(0xffffffffu, ss, o);
    float inv = 1.f / fmaxf(sqrtf(ss), 1e-12f);
    float2 o2 = make_float2(acc.x * inv, acc.y * inv);
    if (!LAST) eh_out[(size_t)warp * 32 + lane] = __float22half2_rn(o2);
    float2 cur = HOP0 ? base_ent[(size_t)warp * 32 + lane]
                      : res_ent[(size_t)warp * 32 + lane];
    cur.x += o2.x; cur.y += o2.y;
    res_ent[(size_t)warp * 32 + lane] = cur;
}

// ---------------- user gather (8-deep unroll + rolled remainder) ----------------
template <bool HOP0, bool LAST>
__global__ void __launch_bounds__(256)
usr_gather_kernel(const __half2* __restrict__ eh,
                  float* __restrict__ u_out,
                  const float2* __restrict__ base_usr, float2* __restrict__ res_usr) {
    __shared__ float2 s_rs[32];
    if (threadIdx.x < 32) s_rs[threadIdx.x] = ((const float2*)g_relsum)[threadIdx.x];
    __syncthreads();

    int warp = (blockIdx.x * blockDim.x + threadIdx.x) >> 5;
    int lane = threadIdx.x & 31;
    if (warp >= N_USERS) return;
    int uidx = warp;
    float2 rs = s_rs[lane];
    const float* ucrow = g_ucls + (size_t)uidx * N_CLUSTERS;
    float2 acc = make_float2(0.f, 0.f);

    // im segment
    {
        int start = g_offsets[IM_SEG0 + uidx] - IM_BASE;
        int cnt   = g_counts[IM_SEG0 + uidx];
        const int2* ep = g_im + start;
        int j = 0;
        for (; j + 8 <= cnt; j += 8) {
            int2 a[8];
#pragma unroll
            for (int q = 0; q < 8; q++) a[q] = ep[j + q];
            float2 v[8];
#pragma unroll
            for (int q = 0; q < 8; q++) v[q] = __half22float2(eh[(size_t)a[q].x * 32 + lane]);
#pragma unroll
            for (int q = 0; q < 8; q++) {
                float w = __int_as_float(a[q].y);
                acc.x += w * v[q].x;
                acc.y += w * v[q].y;
            }
        }
        for (; j < cnt; j++) {
            int2 a = ep[j];
            float2 v = __half22float2(eh[(size_t)a.x * 32 + lane]);
            float w = __int_as_float(a.y);
            acc.x += w * v.x;
            acc.y += w * v.y;
        }
    }
    // icm segment (fused dw einsum)
    float2 acc2 = make_float2(0.f, 0.f);
    {
        int start = g_offsets[ICM_SEG0 + uidx] - ICM_BASE;
        int cnt   = g_counts[ICM_SEG0 + uidx];
        const int2* ep = g_icm + start;
        int j = 0;
        for (; j + 8 <= cnt; j += 8) {
            int2 a[8];
#pragma unroll
            for (int q = 0; q < 8; q++) a[q] = ep[j + q];
            float w[8];
#pragma unroll
            for (int q = 0; q < 8; q++)
                w[q] = __int_as_float(a[q].y) * ucrow[a[q].x >> 16];
            float2 v[8];
#pragma unroll
            for (int q = 0; q < 8; q++)
                v[q] = __half22float2(eh[(size_t)(a[q].x & 0xFFFF) * 32 + lane]);
#pragma unroll
            for (int q = 0; q < 8; q++) {
                acc2.x += w[q] * v[q].x;
                acc2.y += w[q] * v[q].y;
            }
        }
        for (; j < cnt; j++) {
            int2 a = ep[j];
            int c = a.x & 0xFFFF, k = a.x >> 16;
            float w = __int_as_float(a.y) * ucrow[k];
            float2 v = __half22float2(eh[(size_t)c * 32 + lane]);
            acc2.x += w * v.x;
            acc2.y += w * v.y;
        }
    }
    acc.x += acc2.x * rs.x;
    acc.y += acc2.y * rs.y;

    float ss = acc.x * acc.x + acc.y * acc.y;
#pragma unroll
    for (int o = 16; o; o >>= 1) ss += __shfl_xor_sync(0xffffffffu, ss, o);
    float inv = 1.f / fmaxf(sqrtf(ss), 1e-12f);
    float2 o2 = make_float2(acc.x * inv, acc.y * inv);
    if (!LAST) ((float2*)(u_out + (size_t)uidx * D))[lane] = o2;
    float2 cur = HOP0 ? base_usr[(size_t)uidx * 32 + lane]
                      : res_usr[(size_t)uidx * 32 + lane];
    cur.x += o2.x; cur.y += o2.y;
    res_usr[(size_t)uidx * 32 + lane] = cur;
}

// ---------------- cor loss ----------------
__global__ void cor_kernel(const float* __restrict__ dw, float* __restrict__ out) {
    float nt[N_FACTORS][N_REL];
#pragma unroll
    for (int c = 0; c < N_FACTORS; c++) {
        float ss = 0.f;
#pragma unroll
        for (int k = 0; k < N_REL; k++) { float x = dw[c * N_REL + k]; ss += x * x; }
        float inv = 1.f / fmaxf(sqrtf(ss), 1e-12f);
#pragma unroll
        for (int k = 0; k < N_REL; k++) nt[c][k] = dw[c * N_REL + k] * inv;
    }
    float loss = 0.f;
#pragma unroll
    for (int i = 0; i < N_FACTORS; i++) {
        float ssum = 0.f, diag = 0.f;
#pragma unroll
        for (int j = 0; j < N_FACTORS; j++) {
            float dot = 0.f;
#pragma unroll
            for (int k = 0; k < N_REL; k++) dot += nt[i][k] * nt[j][k];
            float s = expf(dot / TMP);
            ssum += s;
            if (i == j) diag = s;
        }
        loss -= logf(diag / ssum);
    }
    out[0] = loss;
}

// ---------------- launch ----------------
extern "C" void kernel_launch(void* const* d_in, const int* in_sizes, int n_in,
                              void* d_out, int out_size) {
    const float* user_emb     = (const float*)d_in[0];
    const float* entity_emb   = (const float*)d_in[1];
    const float* relation_emb = (const float*)d_in[3];
    const float* disen        = (const float*)d_in[4];
    const float* usr_cls_w    = (const float*)d_in[5];
    const float* edge_imp     = (const float*)d_in[6];
    const float* im_vals      = (const float*)d_in[7];
    const float* icm_vals     = (const float*)d_in[8];
    const int*   edge_index   = (const int*)d_in[9];
    const int*   edge_type    = (const int*)d_in[10];
    const int*   im_rows      = (const int*)d_in[11];
    const int*   im_cols      = (const int*)d_in[12];
    const int*   icm_cls      = (const int*)d_in[13];
    const int*   icm_rows     = (const int*)d_in[14];
    const int*   icm_cols     = (const int*)d_in[15];

    float* out     = (float*)d_out;
    float* out_ent = out;
    float* out_usr = out + (size_t)N_ENTITIES * D;
    float* out_cor = out + (size_t)N_ENTITIES * D + (size_t)N_USERS * D;

    __half *p_ehA, *p_ehB;
    float *p_u;
    cudaGetSymbolAddress((void**)&p_ehA, g_ehA);
    cudaGetSymbolAddress((void**)&p_ehB, g_ehB);
    cudaGetSymbolAddress((void**)&p_u, g_u);

    static cudaStream_t s1 = nullptr, s2 = nullptr;
    static cudaEvent_t ev_fork = nullptr, ev_prep = nullptr, ev_scan = nullptr,
                       ev_ent0 = nullptr, ev_usr = nullptr;
    if (s1 == nullptr) {
        cudaStreamCreateWithFlags(&s1, cudaStreamNonBlocking);
        cudaStreamCreateWithFlags(&s2, cudaStreamNonBlocking);
        cudaEventCreateWithFlags(&ev_fork, cudaEventDisableTiming);
        cudaEventCreateWithFlags(&ev_prep, cudaEventDisableTiming);
        cudaEventCreateWithFlags(&ev_scan, cudaEventDisableTiming);
        cudaEventCreateWithFlags(&ev_ent0, cudaEventDisableTiming);
        cudaEventCreateWithFlags(&ev_usr, cudaEventDisableTiming);
    }

    const int TPB = 256;
    unsigned ablocks  = (N_ENTITIES + N_USERS + TPB - 1) / TPB;
    unsigned eblocks  = (N_ENTITIES + TPB - 1) / TPB;
    unsigned ublocks  = (N_USERS + TPB - 1) / TPB;
    unsigned egblocks = (unsigned)(((long long)N_ENTITIES * 32 + TPB - 1) / TPB);
    unsigned ugblocks = (unsigned)(((long long)N_USERS * 32 + TPB - 1) / TPB);

    // ---- fork s1: convert+relsum, hop-0 att/ucls, cor ----
    cudaEventRecord(ev_fork, 0);
    cudaStreamWaitEvent(s1, ev_fork, 0);
    cudaStreamWaitEvent(s2, ev_fork, 0);
    convert_kernel<<<(CONV_N + TPB - 1) / TPB, TPB, 0, s1>>>(
        (const float2*)entity_emb, (__half2*)p_ehA, relation_emb);
    attucls0_kernel<<<ablocks, TPB, 0, s1>>>(entity_emb, user_emb, relation_emb, usr_cls_w);
    cor_kernel<<<1, 1, 0, s1>>>(disen, out_cor);
    cudaEventRecord(ev_prep, s1);

    // ---- main: count + scan ----
    zero_counts_kernel<<<(N_SEGS + TPB - 1) / TPB, TPB>>>();
    count_kernel<<<(TOT_NNZ + TPB - 1) / TPB, TPB>>>(edge_index, im_rows, icm_rows);
    scanA_kernel<<<N_TILES, SCAN_TILE>>>();
    scanB_kernel<<<1, 256>>>();
    scanC_kernel<<<N_TILES, SCAN_TILE>>>();
    cudaEventRecord(ev_scan, 0);

    // ---- s2: im/icm fill + user chain ----
    cudaStreamWaitEvent(s2, ev_scan, 0);
    fill_imicm_kernel<<<(NNZ_IMICM + TPB - 1) / TPB, TPB, 0, s2>>>(
        im_rows, im_cols, im_vals, icm_rows, icm_cols, icm_cls, icm_vals);
    cudaStreamWaitEvent(s2, ev_prep, 0);
    usr_gather_kernel<true, false><<<ugblocks, TPB, 0, s2>>>(
        (const __half2*)p_ehA, p_u, (const float2*)user_emb, (float2*)out_usr);
    ucls_u_kernel<<<ublocks, TPB, 0, s2>>>(p_u, usr_cls_w);

    // ---- main: edge fill + entity chain ----
    fill_edge_kernel<<<(N_EDGES + TPB - 1) / TPB, TPB>>>(
        edge_index, edge_index + N_EDGES, edge_type, edge_imp);
    cudaStreamWaitEvent(0, ev_prep, 0);
    ent_gather_kernel<true, false><<<egblocks, TPB>>>(
        (const __half2*)p_ehA, relation_emb, (__half2*)p_ehB,
        (const float2*)entity_emb, (float2*)out_ent);
    cudaEventRecord(ev_ent0, 0);

    // ---- s2: hop-1 user gather (needs ehB + ucls1) ----
    cudaStreamWaitEvent(s2, ev_ent0, 0);
    usr_gather_kernel<false, true><<<ugblocks, TPB, 0, s2>>>(
        (const __half2*)p_ehB, p_u, nullptr, (float2*)out_usr);
    cudaEventRecord(ev_usr, s2);

    // ---- main: hop-1 entity att + gather ----
    att_e_kernel<<<eblocks, TPB>>>((const __half2*)p_ehB, relation_emb);
    ent_gather_kernel<false, true><<<egblocks, TPB>>>(
        (const __half2*)p_ehB, relation_emb, (__half2*)p_ehA,
        nullptr, (float2*)out_ent);

    // ---- join all ----
    cudaStreamWaitEvent(0, ev_usr, 0);
}

// round 16
// speedup vs baseline: 1.2729x; 1.0034x over previous
#include <cuda_runtime.h>
#include <cuda_fp16.h>
#include <cstdint>

#define N_ENTITIES 100000
#define N_USERS    50000
#define N_ITEMS    30000
#define D          64
#define N_REL      16
#define N_FACTORS  4
#define N_CLUSTERS 4
#define N_EDGES    1500000
#define NNZ_IM     1000000
#define NNZ_ICM    1000000
#define N_HOPS     2
#define TMP        0.2f

#define N_SEGS     (N_ENTITIES + N_USERS + N_USERS)   // 200000
#define IM_SEG0    N_ENTITIES
#define ICM_SEG0   (N_ENTITIES + N_USERS)
#define IM_BASE    N_EDGES
#define ICM_BASE   (N_EDGES + NNZ_IM)
#define TOT_NNZ    (N_EDGES + NNZ_IM + NNZ_ICM)       // 3.5M
#define NNZ_IMICM  (NNZ_IM + NNZ_ICM)                 // 2M

#define SCAN_TILE  1024
#define N_TILES    ((N_SEGS + SCAN_TILE - 1) / SCAN_TILE)   // 196

#define CONV_N     (N_ENTITIES * D / 2)

// ---------------- scratch ----------------
__device__ float  g_att [N_ENTITIES * N_REL];
__device__ float  g_ucls[N_USERS * N_CLUSTERS];
__device__ __half g_ehA [N_ENTITIES * D];
__device__ __half g_ehB [N_ENTITIES * D];
__device__ float  g_u   [N_USERS * D];
__device__ float  g_relsum[D];

__device__ int   g_counts  [N_SEGS];
__device__ int   g_offsets [N_SEGS];
__device__ int   g_cursor  [N_SEGS];
__device__ int   g_tilesum [N_TILES];
__device__ int   g_tilebase[N_TILES];
__device__ int2  g_edge [N_EDGES];   // {tail | etype<<20, imp bits}
__device__ int2  g_im   [NNZ_IM];    // {col, val bits}
__device__ int2  g_icm  [NNZ_ICM];   // {col | cls<<16, val bits}

// ---------------- side-stream prep ----------------
__global__ void convert_kernel(const float2* __restrict__ e2, __half2* __restrict__ eh,
                               const float* __restrict__ rel) {
    int i = blockIdx.x * blockDim.x + threadIdx.x;
    if (i < CONV_N) eh[i] = __float22half2_rn(e2[i]);
    if (i < D) {
        float s = 0.f;
#pragma unroll
        for (int r = 0; r < N_REL; r++) s += rel[r * D + i];
        g_relsum[i] = s;
    }
}

// ---------------- build ----------------
__global__ void zero_counts_kernel() {
    int i = blockIdx.x * blockDim.x + threadIdx.x;
    if (i < N_SEGS) g_counts[i] = 0;
}

__global__ void count_kernel(const int* __restrict__ head,
                             const int* __restrict__ im_rows,
                             const int* __restrict__ icm_rows) {
    int i = blockIdx.x * blockDim.x + threadIdx.x;
    if (i < N_EDGES) {
        atomicAdd(&g_counts[head[i]], 1);
    } else if (i < N_EDGES + NNZ_IM) {
        atomicAdd(&g_counts[IM_SEG0 + im_rows[i - N_EDGES]], 1);
    } else if (i < TOT_NNZ) {
        atomicAdd(&g_counts[ICM_SEG0 + icm_rows[i - N_EDGES - NNZ_IM]], 1);
    }
}

__global__ void scanA_kernel() {
    __shared__ int s[SCAN_TILE];
    int idx = blockIdx.x * SCAN_TILE + threadIdx.x;
    s[threadIdx.x] = (idx < N_SEGS) ? g_counts[idx] : 0;
    __syncthreads();
    for (int off = SCAN_TILE / 2; off > 0; off >>= 1) {
        if (threadIdx.x < off) s[threadIdx.x] += s[threadIdx.x + off];
        __syncthreads();
    }
    if (threadIdx.x == 0) g_tilesum[blockIdx.x] = s[0];
}

__global__ void scanB_kernel() {
    __shared__ int s[256];
    int t = threadIdx.x;
    int v = (t < N_TILES) ? g_tilesum[t] : 0;
    s[t] = v;
    __syncthreads();
    for (int off = 1; off < 256; off <<= 1) {
        int w = (t >= off) ? s[t - off] : 0;
        __syncthreads();
        s[t] += w;
        __syncthreads();
    }
    if (t < N_TILES) g_tilebase[t] = s[t] - v;
}

__global__ void scanC_kernel() {
    __shared__ int s[SCAN_TILE];
    int t = threadIdx.x;
    int idx = blockIdx.x * SCAN_TILE + t;
    int v = (idx < N_SEGS) ? g_counts[idx] : 0;
    s[t] = v;
    __syncthreads();
    for (int off = 1; off < SCAN_TILE; off <<= 1) {
        int w = (t >= off) ? s[t - off] : 0;
        __syncthreads();
        s[t] += w;
        __syncthreads();
    }
    if (idx < N_SEGS) {
        int excl = g_tilebase[blockIdx.x] + s[t] - v;
        g_offsets[idx] = excl;
        g_cursor[idx]  = excl;
    }
}

__global__ void fill_edge_kernel(const int* __restrict__ head, const int* __restrict__ tail,
                                 const int* __restrict__ etype, const float* __restrict__ eimp) {
    int i = blockIdx.x * blockDim.x + threadIdx.x;
    if (i < N_EDGES) {
        int h = head[i];
        int pos = atomicAdd(&g_cursor[h], 1);
        g_edge[pos] = make_int2(tail[i] | (etype[i] << 20), __float_as_int(eimp[i]));
    }
}

__global__ void fill_imicm_kernel(const int* __restrict__ im_rows, const int* __restrict__ im_cols,
                                  const float* __restrict__ im_vals,
                                  const int* __restrict__ icm_rows, const int* __restrict__ icm_cols,
                                  const int* __restrict__ icm_cls, const float* __restrict__ icm_vals) {
    int i = blockIdx.x * blockDim.x + threadIdx.x;
    if (i < NNZ_IM) {
        int r = im_rows[i];
        int pos = atomicAdd(&g_cursor[IM_SEG0 + r], 1) - IM_BASE;
        g_im[pos] = make_int2(im_cols[i], __float_as_int(im_vals[i]));
    } else if (i < NNZ_IMICM) {
        int j = i - NNZ_IM;
        int r = icm_rows[j];
        int pos = atomicAdd(&g_cursor[ICM_SEG0 + r], 1) - ICM_BASE;
        g_icm[pos] = make_int2(icm_cols[j] | (icm_cls[j] << 16), __float_as_int(icm_vals[j]));
    }
}

// ---------------- hop-0 att+ucls (fp32 inputs) ----------------
__global__ void attucls0_kernel(const float* __restrict__ e, const float* __restrict__ u,
                                const float* __restrict__ rel, const float* __restrict__ w) {
    __shared__ float s_rel[N_REL * D];
    __shared__ float s_w[N_CLUSTERS * D];
    for (int i = threadIdx.x; i < N_REL * D; i += blockDim.x) s_rel[i] = rel[i];
    for (int i = threadIdx.x; i < N_CLUSTERS * D; i += blockDim.x) s_w[i] = w[i];
    __syncthreads();
    int i = blockIdx.x * blockDim.x + threadIdx.x;
    if (i < N_ENTITIES) {
        const float4* row = (const float4*)(e + (size_t)i * D);
        float acc[N_REL];
#pragma unroll
        for (int r = 0; r < N_REL; r++) acc[r] = 0.f;
#pragma unroll
        for (int k = 0; k < D / 4; k++) {
            float4 ev = row[k];
#pragma unroll
            for (int r = 0; r < N_REL; r++) {
                float4 rv = ((const float4*)(s_rel + r * D))[k];
                acc[r] += ev.x * rv.x + ev.y * rv.y + ev.z * rv.z + ev.w * rv.w;
            }
        }
        float mx = acc[0];
#pragma unroll
        for (int r = 1; r < N_REL; r++) mx = fmaxf(mx, acc[r]);
        float sum = 0.f;
#pragma unroll
        for (int r = 0; r < N_REL; r++) { acc[r] = expf(acc[r] - mx); sum += acc[r]; }
        float inv = 1.f / sum;
#pragma unroll
        for (int r = 0; r < N_REL; r++) g_att[(size_t)i * N_REL + r] = acc[r] * inv;
    } else if (i < N_ENTITIES + N_USERS) {
        int uidx = i - N_ENTITIES;
        const float4* row = (const float4*)(u + (size_t)uidx * D);
        float acc[N_CLUSTERS] = {0.f, 0.f, 0.f, 0.f};
#pragma unroll
        for (int k = 0; k < D / 4; k++) {
            float4 uv = row[k];
#pragma unroll
            for (int c = 0; c < N_CLUSTERS; c++) {
                float4 wv = ((const float4*)(s_w + c * D))[k];
                acc[c] += uv.x * wv.x + uv.y * wv.y + uv.z * wv.z + uv.w * wv.w;
            }
        }
        float mx = fmaxf(fmaxf(acc[0], acc[1]), fmaxf(acc[2], acc[3]));
        float sum = 0.f;
#pragma unroll
        for (int c = 0; c < N_CLUSTERS; c++) { acc[c] = expf(acc[c] - mx); sum += acc[c]; }
        float inv = 1.f / sum;
#pragma unroll
        for (int c = 0; c < N_CLUSTERS; c++) g_ucls[(size_t)uidx * N_CLUSTERS + c] = acc[c] * inv;
    }
}

// ---------------- hop-1 att (entity, fp16 source) ----------------
__global__ void att_e_kernel(const __half2* __restrict__ eh, const float* __restrict__ rel) {
    __shared__ float s_rel[N_REL * D];
    for (int i = threadIdx.x; i < N_REL * D; i += blockDim.x) s_rel[i] = rel[i];
    __syncthreads();
    int i = blockIdx.x * blockDim.x + threadIdx.x;
    if (i >= N_ENTITIES) return;
    const __half2* row = eh + (size_t)i * (D / 2);
    float acc[N_REL];
#pragma unroll
    for (int r = 0; r < N_REL; r++) acc[r] = 0.f;
#pragma unroll
    for (int k = 0; k < D / 2; k++) {
        float2 ev = __half22float2(row[k]);
#pragma unroll
        for (int r = 0; r < N_REL; r++) {
            float2 rv = ((const float2*)(s_rel + r * D))[k];
            acc[r] += ev.x * rv.x + ev.y * rv.y;
        }
    }
    float mx = acc[0];
#pragma unroll
    for (int r = 1; r < N_REL; r++) mx = fmaxf(mx, acc[r]);
    float sum = 0.f;
#pragma unroll
    for (int r = 0; r < N_REL; r++) { acc[r] = expf(acc[r] - mx); sum += acc[r]; }
    float inv = 1.f / sum;
#pragma unroll
    for (int r = 0; r < N_REL; r++) g_att[(size_t)i * N_REL + r] = acc[r] * inv;
}

// ---------------- hop-1 ucls ----------------
__global__ void ucls_u_kernel(const float* __restrict__ u, const float* __restrict__ w) {
    __shared__ float s_w[N_CLUSTERS * D];
    for (int i = threadIdx.x; i < N_CLUSTERS * D; i += blockDim.x) s_w[i] = w[i];
    __syncthreads();
    int i = blockIdx.x * blockDim.x + threadIdx.x;
    if (i >= N_USERS) return;
    const float4* row = (const float4*)(u + (size_t)i * D);
    float acc[N_CLUSTERS] = {0.f, 0.f, 0.f, 0.f};
#pragma unroll
    for (int k = 0; k < D / 4; k++) {
        float4 uv = row[k];
#pragma unroll
        for (int c = 0; c < N_CLUSTERS; c++) {
            float4 wv = ((const float4*)(s_w + c * D))[k];
            acc[c] += uv.x * wv.x + uv.y * wv.y + uv.z * wv.z + uv.w * wv.w;
        }
    }
    float mx = fmaxf(fmaxf(acc[0], acc[1]), fmaxf(acc[2], acc[3]));
    float sum = 0.f;
#pragma unroll
    for (int c = 0; c < N_CLUSTERS; c++) { acc[c] = expf(acc[c] - mx); sum += acc[c]; }
    float inv = 1.f / sum;
#pragma unroll
    for (int c = 0; c < N_CLUSTERS; c++) g_ucls[(size_t)i * N_CLUSTERS + c] = acc[c] * inv;
}

// ---------------- entity gather (8-deep unroll + rolled remainder) ----------------
template <bool HOP0, bool LAST>
__global__ void __launch_bounds__(256)
ent_gather_kernel(const __half2* __restrict__ eh,
                  const float* __restrict__ rel,
                  __half2* __restrict__ eh_out,
                  const float2* __restrict__ base_ent, float2* __restrict__ res_ent) {
    __shared__ float2 s_rel[N_REL * 32];
    for (int i = threadIdx.x; i < N_REL * 32; i += blockDim.x)
        s_rel[i] = ((const float2*)rel)[i];
    __syncthreads();

    int warp = (blockIdx.x * blockDim.x + threadIdx.x) >> 5;
    int lane = threadIdx.x & 31;
    if (warp >= N_ENTITIES) return;
    float2 acc = make_float2(0.f, 0.f);

    int start = g_offsets[warp];
    int cnt   = g_counts[warp];
    const int2* ep = g_edge + start;
    const float* attrow = g_att + (size_t)warp * N_REL;
    int j = 0;
    for (; j + 8 <= cnt; j += 8) {
        int2 a[8];
#pragma unroll
        for (int q = 0; q < 8; q++) a[q] = ep[j + q];
        float w[8];
        int t[8], r[8];
#pragma unroll
        for (int q = 0; q < 8; q++) {
            t[q] = a[q].x & 0xFFFFF;
            r[q] = a[q].x >> 20;
            w[q] = __int_as_float(a[q].y) * attrow[r[q]];
        }
        float2 v[8];
#pragma unroll
        for (int q = 0; q < 8; q++) v[q] = __half22float2(eh[(size_t)t[q] * 32 + lane]);
#pragma unroll
        for (int q = 0; q < 8; q++) {
            float2 qr = s_rel[r[q] * 32 + lane];
            acc.x += w[q] * v[q].x * qr.x;
            acc.y += w[q] * v[q].y * qr.y;
        }
    }
    for (; j < cnt; j++) {
        int2 a = ep[j];
        int t = a.x & 0xFFFFF, r = a.x >> 20;
        float wv = __int_as_float(a.y) * attrow[r];
        float2 v = __half22float2(eh[(size_t)t * 32 + lane]);
        float2 q = s_rel[r * 32 + lane];
        acc.x += wv * v.x * q.x;
        acc.y += wv * v.y * q.y;
    }
    float ss = acc.x * acc.x + acc.y * acc.y;
#pragma unroll
    for (int o = 16; o; o >>= 1) ss += __shfl_xor_sync(0xffffffffu, ss, o);
    float inv = 1.f / fmaxf(sqrtf(ss), 1e-12f);
    float2 o2 = make_float2(acc.x * inv, acc.y * inv);
    if (!LAST) eh_out[(size_t)warp * 32 + lane] = __float22half2_rn(o2);
    float2 cur = HOP0 ? base_ent[(size_t)warp * 32 + lane]
                      : res_ent[(size_t)warp * 32 + lane];
    cur.x += o2.x; cur.y += o2.y;
    res_ent[(size_t)warp * 32 + lane] = cur;
}

// ---------------- user gather (8-deep unroll + rolled remainder) ----------------
template <bool HOP0, bool LAST>
__global__ void __launch_bounds__(256)
usr_gather_kernel(const __half2* __restrict__ eh,
                  float* __restrict__ u_out,
                  const float2* __restrict__ base_usr, float2* __restrict__ res_usr) {
    __shared__ float2 s_rs[32];
    if (threadIdx.x < 32) s_rs[threadIdx.x] = ((const float2*)g_relsum)[threadIdx.x];
    __syncthreads();

    int warp = (blockIdx.x * blockDim.x + threadIdx.x) >> 5;
    int lane = threadIdx.x & 31;
    if (warp >= N_USERS) return;
    int uidx = warp;
    float2 rs = s_rs[lane];
    const float* ucrow = g_ucls + (size_t)uidx * N_CLUSTERS;
    float2 acc = make_float2(0.f, 0.f);

    // im segment
    {
        int start = g_offsets[IM_SEG0 + uidx] - IM_BASE;
        int cnt   = g_counts[IM_SEG0 + uidx];
        const int2* ep = g_im + start;
        int j = 0;
        for (; j + 8 <= cnt; j += 8) {
            int2 a[8];
#pragma unroll
            for (int q = 0; q < 8; q++) a[q] = ep[j + q];
            float2 v[8];
#pragma unroll
            for (int q = 0; q < 8; q++) v[q] = __half22float2(eh[(size_t)a[q].x * 32 + lane]);
#pragma unroll
            for (int q = 0; q < 8; q++) {
                float w = __int_as_float(a[q].y);
                acc.x += w * v[q].x;
                acc.y += w * v[q].y;
            }
        }
        for (; j < cnt; j++) {
            int2 a = ep[j];
            float2 v = __half22float2(eh[(size_t)a.x * 32 + lane]);
            float w = __int_as_float(a.y);
            acc.x += w * v.x;
            acc.y += w * v.y;
        }
    }
    // icm segment (fused dw einsum)
    float2 acc2 = make_float2(0.f, 0.f);
    {
        int start = g_offsets[ICM_SEG0 + uidx] - ICM_BASE;
        int cnt   = g_counts[ICM_SEG0 + uidx];
        const int2* ep = g_icm + start;
        int j = 0;
        for (; j + 8 <= cnt; j += 8) {
            int2 a[8];
#pragma unroll
            for (int q = 0; q < 8; q++) a[q] = ep[j + q];
            float w[8];
#pragma unroll
            for (int q = 0; q < 8; q++)
                w[q] = __int_as_float(a[q].y) * ucrow[a[q].x >> 16];
            float2 v[8];
#pragma unroll
            for (int q = 0; q < 8; q++)
                v[q] = __half22float2(eh[(size_t)(a[q].x & 0xFFFF) * 32 + lane]);
#pragma unroll
            for (int q = 0; q < 8; q++) {
                acc2.x += w[q] * v[q].x;
                acc2.y += w[q] * v[q].y;
            }
        }
        for (; j < cnt; j++) {
            int2 a = ep[j];
            int c = a.x & 0xFFFF, k = a.x >> 16;
            float w = __int_as_float(a.y) * ucrow[k];
            float2 v = __half22float2(eh[(size_t)c * 32 + lane]);
            acc2.x += w * v.x;
            acc2.y += w * v.y;
        }
    }
    acc.x += acc2.x * rs.x;
    acc.y += acc2.y * rs.y;

    float ss = acc.x * acc.x + acc.y * acc.y;
#pragma unroll
    for (int o = 16; o; o >>= 1) ss += __shfl_xor_sync(0xffffffffu, ss, o);
    float inv = 1.f / fmaxf(sqrtf(ss), 1e-12f);
    float2 o2 = make_float2(acc.x * inv, acc.y * inv);
    if (!LAST) ((float2*)(u_out + (size_t)uidx * D))[lane] = o2;
    float2 cur = HOP0 ? base_usr[(size_t)uidx * 32 + lane]
                      : res_usr[(size_t)uidx * 32 + lane];
    cur.x += o2.x; cur.y += o2.y;
    res_usr[(size_t)uidx * 32 + lane] = cur;
}

// ---------------- cor loss ----------------
__global__ void cor_kernel(const float* __restrict__ dw, float* __restrict__ out) {
    float nt[N_FACTORS][N_REL];
#pragma unroll
    for (int c = 0; c < N_FACTORS; c++) {
        float ss = 0.f;
#pragma unroll
        for (int k = 0; k < N_REL; k++) { float x = dw[c * N_REL + k]; ss += x * x; }
        float inv = 1.f / fmaxf(sqrtf(ss), 1e-12f);
#pragma unroll
        for (int k = 0; k < N_REL; k++) nt[c][k] = dw[c * N_REL + k] * inv;
    }
    float loss = 0.f;
#pragma unroll
    for (int i = 0; i < N_FACTORS; i++) {
        float ssum = 0.f, diag = 0.f;
#pragma unroll
        for (int j = 0; j < N_FACTORS; j++) {
            float dot = 0.f;
#pragma unroll
            for (int k = 0; k < N_REL; k++) dot += nt[i][k] * nt[j][k];
            float s = expf(dot / TMP);
            ssum += s;
            if (i == j) diag = s;
        }
        loss -= logf(diag / ssum);
    }
    out[0] = loss;
}

// ---------------- launch ----------------
extern "C" void kernel_launch(void* const* d_in, const int* in_sizes, int n_in,
                              void* d_out, int out_size) {
    const float* user_emb     = (const float*)d_in[0];
    const float* entity_emb   = (const float*)d_in[1];
    const float* relation_emb = (const float*)d_in[3];
    const float* disen        = (const float*)d_in[4];
    const float* usr_cls_w    = (const float*)d_in[5];
    const float* edge_imp     = (const float*)d_in[6];
    const float* im_vals      = (const float*)d_in[7];
    const float* icm_vals     = (const float*)d_in[8];
    const int*   edge_index   = (const int*)d_in[9];
    const int*   edge_type    = (const int*)d_in[10];
    const int*   im_rows      = (const int*)d_in[11];
    const int*   im_cols      = (const int*)d_in[12];
    const int*   icm_cls      = (const int*)d_in[13];
    const int*   icm_rows     = (const int*)d_in[14];
    const int*   icm_cols     = (const int*)d_in[15];

    float* out     = (float*)d_out;
    float* out_ent = out;
    float* out_usr = out + (size_t)N_ENTITIES * D;
    float* out_cor = out + (size_t)N_ENTITIES * D + (size_t)N_USERS * D;

    __half *p_ehA, *p_ehB;
    float *p_u;
    cudaGetSymbolAddress((void**)&p_ehA, g_ehA);
    cudaGetSymbolAddress((void**)&p_ehB, g_ehB);
    cudaGetSymbolAddress((void**)&p_u, g_u);

    static cudaStream_t s1 = nullptr, s2 = nullptr;
    static cudaEvent_t ev_fork = nullptr, ev_prep = nullptr, ev_scan = nullptr,
                       ev_ent0 = nullptr, ev_usr = nullptr;
    if (s1 == nullptr) {
        cudaStreamCreateWithFlags(&s1, cudaStreamNonBlocking);
        cudaStreamCreateWithFlags(&s2, cudaStreamNonBlocking);
        cudaEventCreateWithFlags(&ev_fork, cudaEventDisableTiming);
        cudaEventCreateWithFlags(&ev_prep, cudaEventDisableTiming);
        cudaEventCreateWithFlags(&ev_scan, cudaEventDisableTiming);
        cudaEventCreateWithFlags(&ev_ent0, cudaEventDisableTiming);
        cudaEventCreateWithFlags(&ev_usr, cudaEventDisableTiming);
    }

    const int TPB = 256;
    unsigned ablocks  = (N_ENTITIES + N_USERS + TPB - 1) / TPB;
    unsigned eblocks  = (N_ENTITIES + TPB - 1) / TPB;
    unsigned ublocks  = (N_USERS + TPB - 1) / TPB;
    unsigned egblocks = (unsigned)(((long long)N_ENTITIES * 32 + TPB - 1) / TPB);
    unsigned ugblocks = (unsigned)(((long long)N_USERS * 32 + TPB - 1) / TPB);

    // ---- fork s1: convert+relsum, hop-0 att/ucls, cor ----
    cudaEventRecord(ev_fork, 0);
    cudaStreamWaitEvent(s1, ev_fork, 0);
    cudaStreamWaitEvent(s2, ev_fork, 0);
    convert_kernel<<<(CONV_N + TPB - 1) / TPB, TPB, 0, s1>>>(
        (const float2*)entity_emb, (__half2*)p_ehA, relation_emb);
    attucls0_kernel<<<ablocks, TPB, 0, s1>>>(entity_emb, user_emb, relation_emb, usr_cls_w);
    cor_kernel<<<1, 1, 0, s1>>>(disen, out_cor);
    cudaEventRecord(ev_prep, s1);

    // ---- main: count + scan ----
    zero_counts_kernel<<<(N_SEGS + TPB - 1) / TPB, TPB>>>();
    count_kernel<<<(TOT_NNZ + TPB - 1) / TPB, TPB>>>(edge_index, im_rows, icm_rows);
    scanA_kernel<<<N_TILES, SCAN_TILE>>>();
    scanB_kernel<<<1, 256>>>();
    scanC_kernel<<<N_TILES, SCAN_TILE>>>();
    cudaEventRecord(ev_scan, 0);

    // ---- s2: im/icm fill + user chain ----
    cudaStreamWaitEvent(s2, ev_scan, 0);
    fill_imicm_kernel<<<(NNZ_IMICM + TPB - 1) / TPB, TPB, 0, s2>>>(
        im_rows, im_cols, im_vals, icm_rows, icm_cols, icm_cls, icm_vals);
    cudaStreamWaitEvent(s2, ev_prep, 0);
    usr_gather_kernel<true, false><<<ugblocks, TPB, 0, s2>>>(
        (const __half2*)p_ehA, p_u, (const float2*)user_emb, (float2*)out_usr);
    ucls_u_kernel<<<ublocks, TPB, 0, s2>>>(p_u, usr_cls_w);

    // ---- main: edge fill + entity chain ----
    fill_edge_kernel<<<(N_EDGES + TPB - 1) / TPB, TPB>>>(
        edge_index, edge_index + N_EDGES, edge_type, edge_imp);
    cudaStreamWaitEvent(0, ev_prep, 0);
    ent_gather_kernel<true, false><<<egblocks, TPB>>>(
        (const __half2*)p_ehA, relation_emb, (__half2*)p_ehB,
        (const float2*)entity_emb, (float2*)out_ent);
    cudaEventRecord(ev_ent0, 0);

    // ---- s2: hop-1 user gather (needs ehB + ucls1) ----
    cudaStreamWaitEvent(s2, ev_ent0, 0);
    usr_gather_kernel<false, true><<<ugblocks, TPB, 0, s2>>>(
        (const __half2*)p_ehB, p_u, nullptr, (float2*)out_usr);
    cudaEventRecord(ev_usr, s2);

    // ---- main: hop-1 entity att + gather ----
    att_e_kernel<<<eblocks, TPB>>>((const __half2*)p_ehB, relation_emb);
    ent_gather_kernel<false, true><<<egblocks, TPB>>>(
        (const __half2*)p_ehB, relation_emb, (__half2*)p_ehA,
        nullptr, (float2*)out_ent);

    // ---- join all ----
    cudaStreamWaitEvent(0, ev_usr, 0);
}

// round 17
// speedup vs baseline: 1.3237x; 1.0399x over previous
#include <cuda_runtime.h>
#include <cuda_fp16.h>
#include <cstdint>

#define N_ENTITIES 100000
#define N_USERS    50000
#define N_ITEMS    30000
#define D          64
#define N_REL      16
#define N_FACTORS  4
#define N_CLUSTERS 4
#define N_EDGES    1500000
#define NNZ_IM     1000000
#define NNZ_ICM    1000000
#define N_HOPS     2
#define TMP        0.2f

#define N_SEGS     (N_ENTITIES + N_USERS + N_USERS)   // 200000
#define IM_SEG0    N_ENTITIES
#define ICM_SEG0   (N_ENTITIES + N_USERS)
#define IM_BASE    N_EDGES
#define ICM_BASE   (N_EDGES + NNZ_IM)
#define NNZ_IMICM  (NNZ_IM + NNZ_ICM)                 // 2M

#define SCAN_TILE  1024
#define NT_ENT     ((N_ENTITIES + SCAN_TILE - 1) / SCAN_TILE)          // 98
#define NT_USR     ((N_USERS * 2 + SCAN_TILE - 1) / SCAN_TILE)         // 98

#define CONV_N     (N_ENTITIES * D / 2)

// ---------------- scratch ----------------
__device__ float  g_att [N_ENTITIES * N_REL];
__device__ float  g_ucls[N_USERS * N_CLUSTERS];
__device__ __half g_ehA [N_ENTITIES * D];
__device__ __half g_ehB [N_ENTITIES * D];
__device__ float  g_u   [N_USERS * D];
__device__ float  g_relsum[D];

__device__ int   g_counts  [N_SEGS];
__device__ int   g_offsets [N_SEGS];
__device__ int   g_cursor  [N_SEGS];
__device__ int   g_tsE [NT_ENT];
__device__ int   g_tbE [NT_ENT];
__device__ int   g_tsU [NT_USR];
__device__ int   g_tbU [NT_USR];
__device__ int2  g_edge [N_EDGES];   // {tail | etype<<20, imp bits}
__device__ int2  g_im   [NNZ_IM];    // {col, val bits}
__device__ int2  g_icm  [NNZ_ICM];   // {col | cls<<16, val bits}

// ---------------- side-stream prep ----------------
__global__ void convert_kernel(const float2* __restrict__ e2, __half2* __restrict__ eh,
                               const float* __restrict__ rel) {
    int i = blockIdx.x * blockDim.x + threadIdx.x;
    if (i < CONV_N) eh[i] = __float22half2_rn(e2[i]);
    if (i < D) {
        float s = 0.f;
#pragma unroll
        for (int r = 0; r < N_REL; r++) s += rel[r * D + i];
        g_relsum[i] = s;
    }
}

// ---------------- build (split pipelines) ----------------
__global__ void zero_range_kernel(int seg0, int n) {
    int i = blockIdx.x * blockDim.x + threadIdx.x;
    if (i < n) g_counts[seg0 + i] = 0;
}

__global__ void count_edge_kernel(const int* __restrict__ head) {
    int i = blockIdx.x * blockDim.x + threadIdx.x;
    if (i < N_EDGES) atomicAdd(&g_counts[head[i]], 1);
}

__global__ void count_imicm_kernel(const int* __restrict__ im_rows,
                                   const int* __restrict__ icm_rows) {
    int i = blockIdx.x * blockDim.x + threadIdx.x;
    if (i < NNZ_IM) {
        atomicAdd(&g_counts[IM_SEG0 + im_rows[i]], 1);
    } else if (i < NNZ_IMICM) {
        atomicAdd(&g_counts[ICM_SEG0 + icm_rows[i - NNZ_IM]], 1);
    }
}

// per-tile sums over [seg0, seg0+nseg)
__global__ void scanA_r_kernel(int seg0, int nseg, int* __restrict__ ts) {
    __shared__ int s[SCAN_TILE];
    int local = blockIdx.x * SCAN_TILE + threadIdx.x;
    s[threadIdx.x] = (local < nseg) ? g_counts[seg0 + local] : 0;
    __syncthreads();
    for (int off = SCAN_TILE / 2; off > 0; off >>= 1) {
        if (threadIdx.x < off) s[threadIdx.x] += s[threadIdx.x + off];
        __syncthreads();
    }
    if (threadIdx.x == 0) ts[blockIdx.x] = s[0];
}

// exclusive scan of <=128 tile sums (one block of 128)
__global__ void scanB_r_kernel(const int* __restrict__ ts, int* __restrict__ tb, int ntiles) {
    __shared__ int s[128];
    int t = threadIdx.x;
    int v = (t < ntiles) ? ts[t] : 0;
    s[t] = v;
    __syncthreads();
    for (int off = 1; off < 128; off <<= 1) {
        int w = (t >= off) ? s[t - off] : 0;
        __syncthreads();
        s[t] += w;
        __syncthreads();
    }
    if (t < ntiles) tb[t] = s[t] - v;
}

// per-tile exclusive scan + tile base + region base
__global__ void scanC_r_kernel(int seg0, int nseg, const int* __restrict__ tb, int base) {
    __shared__ int s[SCAN_TILE];
    int t = threadIdx.x;
    int local = blockIdx.x * SCAN_TILE + t;
    int v = (local < nseg) ? g_counts[seg0 + local] : 0;
    s[t] = v;
    __syncthreads();
    for (int off = 1; off < SCAN_TILE; off <<= 1) {
        int w = (t >= off) ? s[t - off] : 0;
        __syncthreads();
        s[t] += w;
        __syncthreads();
    }
    if (local < nseg) {
        int excl = base + tb[blockIdx.x] + s[t] - v;
        g_offsets[seg0 + local] = excl;
        g_cursor[seg0 + local]  = excl;
    }
}

__global__ void fill_edge_kernel(const int* __restrict__ head, const int* __restrict__ tail,
                                 const int* __restrict__ etype, const float* __restrict__ eimp) {
    int i = blockIdx.x * blockDim.x + threadIdx.x;
    if (i < N_EDGES) {
        int h = head[i];
        int pos = atomicAdd(&g_cursor[h], 1);
        g_edge[pos] = make_int2(tail[i] | (etype[i] << 20), __float_as_int(eimp[i]));
    }
}

__global__ void fill_imicm_kernel(const int* __restrict__ im_rows, const int* __restrict__ im_cols,
                                  const float* __restrict__ im_vals,
                                  const int* __restrict__ icm_rows, const int* __restrict__ icm_cols,
                                  const int* __restrict__ icm_cls, const float* __restrict__ icm_vals) {
    int i = blockIdx.x * blockDim.x + threadIdx.x;
    if (i < NNZ_IM) {
        int r = im_rows[i];
        int pos = atomicAdd(&g_cursor[IM_SEG0 + r], 1) - IM_BASE;
        g_im[pos] = make_int2(im_cols[i], __float_as_int(im_vals[i]));
    } else if (i < NNZ_IMICM) {
        int j = i - NNZ_IM;
        int r = icm_rows[j];
        int pos = atomicAdd(&g_cursor[ICM_SEG0 + r], 1) - ICM_BASE;
        g_icm[pos] = make_int2(icm_cols[j] | (icm_cls[j] << 16), __float_as_int(icm_vals[j]));
    }
}

// ---------------- hop-0 att+ucls (fp32 inputs) ----------------
__global__ void attucls0_kernel(const float* __restrict__ e, const float* __restrict__ u,
                                const float* __restrict__ rel, const float* __restrict__ w) {
    __shared__ float s_rel[N_REL * D];
    __shared__ float s_w[N_CLUSTERS * D];
    for (int i = threadIdx.x; i < N_REL * D; i += blockDim.x) s_rel[i] = rel[i];
    for (int i = threadIdx.x; i < N_CLUSTERS * D; i += blockDim.x) s_w[i] = w[i];
    __syncthreads();
    int i = blockIdx.x * blockDim.x + threadIdx.x;
    if (i < N_ENTITIES) {
        const float4* row = (const float4*)(e + (size_t)i * D);
        float acc[N_REL];
#pragma unroll
        for (int r = 0; r < N_REL; r++) acc[r] = 0.f;
#pragma unroll
        for (int k = 0; k < D / 4; k++) {
            float4 ev = row[k];
#pragma unroll
            for (int r = 0; r < N_REL; r++) {
                float4 rv = ((const float4*)(s_rel + r * D))[k];
                acc[r] += ev.x * rv.x + ev.y * rv.y + ev.z * rv.z + ev.w * rv.w;
            }
        }
        float mx = acc[0];
#pragma unroll
        for (int r = 1; r < N_REL; r++) mx = fmaxf(mx, acc[r]);
        float sum = 0.f;
#pragma unroll
        for (int r = 0; r < N_REL; r++) { acc[r] = expf(acc[r] - mx); sum += acc[r]; }
        float inv = 1.f / sum;
#pragma unroll
        for (int r = 0; r < N_REL; r++) g_att[(size_t)i * N_REL + r] = acc[r] * inv;
    } else if (i < N_ENTITIES + N_USERS) {
        int uidx = i - N_ENTITIES;
        const float4* row = (const float4*)(u + (size_t)uidx * D);
        float acc[N_CLUSTERS] = {0.f, 0.f, 0.f, 0.f};
#pragma unroll
        for (int k = 0; k < D / 4; k++) {
            float4 uv = row[k];
#pragma unroll
            for (int c = 0; c < N_CLUSTERS; c++) {
                float4 wv = ((const float4*)(s_w + c * D))[k];
                acc[c] += uv.x * wv.x + uv.y * wv.y + uv.z * wv.z + uv.w * wv.w;
            }
        }
        float mx = fmaxf(fmaxf(acc[0], acc[1]), fmaxf(acc[2], acc[3]));
        float sum = 0.f;
#pragma unroll
        for (int c = 0; c < N_CLUSTERS; c++) { acc[c] = expf(acc[c] - mx); sum += acc[c]; }
        float inv = 1.f / sum;
#pragma unroll
        for (int c = 0; c < N_CLUSTERS; c++) g_ucls[(size_t)uidx * N_CLUSTERS + c] = acc[c] * inv;
    }
}

// ---------------- hop-1 att (entity, fp16 source) ----------------
__global__ void att_e_kernel(const __half2* __restrict__ eh, const float* __restrict__ rel) {
    __shared__ float s_rel[N_REL * D];
    for (int i = threadIdx.x; i < N_REL * D; i += blockDim.x) s_rel[i] = rel[i];
    __syncthreads();
    int i = blockIdx.x * blockDim.x + threadIdx.x;
    if (i >= N_ENTITIES) return;
    const __half2* row = eh + (size_t)i * (D / 2);
    float acc[N_REL];
#pragma unroll
    for (int r = 0; r < N_REL; r++) acc[r] = 0.f;
#pragma unroll
    for (int k = 0; k < D / 2; k++) {
        float2 ev = __half22float2(row[k]);
#pragma unroll
        for (int r = 0; r < N_REL; r++) {
            float2 rv = ((const float2*)(s_rel + r * D))[k];
            acc[r] += ev.x * rv.x + ev.y * rv.y;
        }
    }
    float mx = acc[0];
#pragma unroll
    for (int r = 1; r < N_REL; r++) mx = fmaxf(mx, acc[r]);
    float sum = 0.f;
#pragma unroll
    for (int r = 0; r < N_REL; r++) { acc[r] = expf(acc[r] - mx); sum += acc[r]; }
    float inv = 1.f / sum;
#pragma unroll
    for (int r = 0; r < N_REL; r++) g_att[(size_t)i * N_REL + r] = acc[r] * inv;
}

// ---------------- hop-1 ucls ----------------
__global__ void ucls_u_kernel(const float* __restrict__ u, const float* __restrict__ w) {
    __shared__ float s_w[N_CLUSTERS * D];
    for (int i = threadIdx.x; i < N_CLUSTERS * D; i += blockDim.x) s_w[i] = w[i];
    __syncthreads();
    int i = blockIdx.x * blockDim.x + threadIdx.x;
    if (i >= N_USERS) return;
    const float4* row = (const float4*)(u + (size_t)i * D);
    float acc[N_CLUSTERS] = {0.f, 0.f, 0.f, 0.f};
#pragma unroll
    for (int k = 0; k < D / 4; k++) {
        float4 uv = row[k];
#pragma unroll
        for (int c = 0; c < N_CLUSTERS; c++) {
            float4 wv = ((const float4*)(s_w + c * D))[k];
            acc[c] += uv.x * wv.x + uv.y * wv.y + uv.z * wv.z + uv.w * wv.w;
        }
    }
    float mx = fmaxf(fmaxf(acc[0], acc[1]), fmaxf(acc[2], acc[3]));
    float sum = 0.f;
#pragma unroll
    for (int c = 0; c < N_CLUSTERS; c++) { acc[c] = expf(acc[c] - mx); sum += acc[c]; }
    float inv = 1.f / sum;
#pragma unroll
    for (int c = 0; c < N_CLUSTERS; c++) g_ucls[(size_t)i * N_CLUSTERS + c] = acc[c] * inv;
}

// ---------------- entity gather (8-deep unroll + rolled remainder) ----------------
template <bool HOP0, bool LAST>
__global__ void __launch_bounds__(256)
ent_gather_kernel(const __half2* __restrict__ eh,
                  const float* __restrict__ rel,
                  __half2* __restrict__ eh_out,
                  const float2* __restrict__ base_ent, float2* __restrict__ res_ent) {
    __shared__ float2 s_rel[N_REL * 32];
    for (int i = threadIdx.x; i < N_REL * 32; i += blockDim.x)
        s_rel[i] = ((const float2*)rel)[i];
    __syncthreads();

    int warp = (blockIdx.x * blockDim.x + threadIdx.x) >> 5;
    int lane = threadIdx.x & 31;
    if (warp >= N_ENTITIES) return;
    float2 acc = make_float2(0.f, 0.f);

    int start = g_offsets[warp];
    int cnt   = g_counts[warp];
    const int2* ep = g_edge + start;
    const float* attrow = g_att + (size_t)warp * N_REL;
    int j = 0;
    for (; j + 8 <= cnt; j += 8) {
        int2 a[8];
#pragma unroll
        for (int q = 0; q < 8; q++) a[q] = ep[j + q];
        float w[8];
        int t[8], r[8];
#pragma unroll
        for (int q = 0; q < 8; q++) {
            t[q] = a[q].x & 0xFFFFF;
            r[q] = a[q].x >> 20;
            w[q] = __int_as_float(a[q].y) * attrow[r[q]];
        }
        float2 v[8];
#pragma unroll
        for (int q = 0; q < 8; q++) v[q] = __half22float2(eh[(size_t)t[q] * 32 + lane]);
#pragma unroll
        for (int q = 0; q < 8; q++) {
            float2 qr = s_rel[r[q] * 32 + lane];
            acc.x += w[q] * v[q].x * qr.x;
            acc.y += w[q] * v[q].y * qr.y;
        }
    }
    for (; j < cnt; j++) {
        int2 a = ep[j];
        int t = a.x & 0xFFFFF, r = a.x >> 20;
        float wv = __int_as_float(a.y) * attrow[r];
        float2 v = __half22float2(eh[(size_t)t * 32 + lane]);
        float2 q = s_rel[r * 32 + lane];
        acc.x += wv * v.x * q.x;
        acc.y += wv * v.y * q.y;
    }
    float ss = acc.x * acc.x + acc.y * acc.y;
#pragma unroll
    for (int o = 16; o; o >>= 1) ss += __shfl_xor_sync(0xffffffffu, ss, o);
    float inv = 1.f / fmaxf(sqrtf(ss), 1e-12f);
    float2 o2 = make_float2(acc.x * inv, acc.y * inv);
    if (!LAST) eh_out[(size_t)warp * 32 + lane] = __float22half2_rn(o2);
    float2 cur = HOP0 ? base_ent[(size_t)warp * 32 + lane]
                      : res_ent[(size_t)warp * 32 + lane];
    cur.x += o2.x; cur.y += o2.y;
    res_ent[(size_t)warp * 32 + lane] = cur;
}

// ---------------- user gather (8-deep unroll + rolled remainder) ----------------
template <bool HOP0, bool LAST>
__global__ void __launch_bounds__(256)
usr_gather_kernel(const __half2* __restrict__ eh,
                  float* __restrict__ u_out,
                  const float2* __restrict__ base_usr, float2* __restrict__ res_usr) {
    __shared__ float2 s_rs[32];
    if (threadIdx.x < 32) s_rs[threadIdx.x] = ((const float2*)g_relsum)[threadIdx.x];
    __syncthreads();

    int warp = (blockIdx.x * blockDim.x + threadIdx.x) >> 5;
    int lane = threadIdx.x & 31;
    if (warp >= N_USERS) return;
    int uidx = warp;
    float2 rs = s_rs[lane];
    const float* ucrow = g_ucls + (size_t)uidx * N_CLUSTERS;
    float2 acc = make_float2(0.f, 0.f);

    // im segment
    {
        int start = g_offsets[IM_SEG0 + uidx] - IM_BASE;
        int cnt   = g_counts[IM_SEG0 + uidx];
        const int2* ep = g_im + start;
        int j = 0;
        for (; j + 8 <= cnt; j += 8) {
            int2 a[8];
#pragma unroll
            for (int q = 0; q < 8; q++) a[q] = ep[j + q];
            float2 v[8];
#pragma unroll
            for (int q = 0; q < 8; q++) v[q] = __half22float2(eh[(size_t)a[q].x * 32 + lane]);
#pragma unroll
            for (int q = 0; q < 8; q++) {
                float w = __int_as_float(a[q].y);
                acc.x += w * v[q].x;
                acc.y += w * v[q].y;
            }
        }
        for (; j < cnt; j++) {
            int2 a = ep[j];
            float2 v = __half22float2(eh[(size_t)a.x * 32 + lane]);
            float w = __int_as_float(a.y);
            acc.x += w * v.x;
            acc.y += w * v.y;
        }
    }
    // icm segment (fused dw einsum)
    float2 acc2 = make_float2(0.f, 0.f);
    {
        int start = g_offsets[ICM_SEG0 + uidx] - ICM_BASE;
        int cnt   = g_counts[ICM_SEG0 + uidx];
        const int2* ep = g_icm + start;
        int j = 0;
        for (; j + 8 <= cnt; j += 8) {
            int2 a[8];
#pragma unroll
            for (int q = 0; q < 8; q++) a[q] = ep[j + q];
            float w[8];
#pragma unroll
            for (int q = 0; q < 8; q++)
                w[q] = __int_as_float(a[q].y) * ucrow[a[q].x >> 16];
            float2 v[8];
#pragma unroll
            for (int q = 0; q < 8; q++)
                v[q] = __half22float2(eh[(size_t)(a[q].x & 0xFFFF) * 32 + lane]);
#pragma unroll
            for (int q = 0; q < 8; q++) {
                acc2.x += w[q] * v[q].x;
                acc2.y += w[q] * v[q].y;
            }
        }
        for (; j < cnt; j++) {
            int2 a = ep[j];
            int c = a.x & 0xFFFF, k = a.x >> 16;
            float w = __int_as_float(a.y) * ucrow[k];
            float2 v = __half22float2(eh[(size_t)c * 32 + lane]);
            acc2.x += w * v.x;
            acc2.y += w * v.y;
        }
    }
    acc.x += acc2.x * rs.x;
    acc.y += acc2.y * rs.y;

    float ss = acc.x * acc.x + acc.y * acc.y;
#pragma unroll
    for (int o = 16; o; o >>= 1) ss += __shfl_xor_sync(0xffffffffu, ss, o);
    float inv = 1.f / fmaxf(sqrtf(ss), 1e-12f);
    float2 o2 = make_float2(acc.x * inv, acc.y * inv);
    if (!LAST) ((float2*)(u_out + (size_t)uidx * D))[lane] = o2;
    float2 cur = HOP0 ? base_usr[(size_t)uidx * 32 + lane]
                      : res_usr[(size_t)uidx * 32 + lane];
    cur.x += o2.x; cur.y += o2.y;
    res_usr[(size_t)uidx * 32 + lane] = cur;
}

// ---------------- cor loss ----------------
__global__ void cor_kernel(const float* __restrict__ dw, float* __restrict__ out) {
    float nt[N_FACTORS][N_REL];
#pragma unroll
    for (int c = 0; c < N_FACTORS; c++) {
        float ss = 0.f;
#pragma unroll
        for (int k = 0; k < N_REL; k++) { float x = dw[c * N_REL + k]; ss += x * x; }
        float inv = 1.f / fmaxf(sqrtf(ss), 1e-12f);
#pragma unroll
        for (int k = 0; k < N_REL; k++) nt[c][k] = dw[c * N_REL + k] * inv;
    }
    float loss = 0.f;
#pragma unroll
    for (int i = 0; i < N_FACTORS; i++) {
        float ssum = 0.f, diag = 0.f;
#pragma unroll
        for (int j = 0; j < N_FACTORS; j++) {
            float dot = 0.f;
#pragma unroll
            for (int k = 0; k < N_REL; k++) dot += nt[i][k] * nt[j][k];
            float s = expf(dot / TMP);
            ssum += s;
            if (i == j) diag = s;
        }
        loss -= logf(diag / ssum);
    }
    out[0] = loss;
}

// ---------------- launch ----------------
extern "C" void kernel_launch(void* const* d_in, const int* in_sizes, int n_in,
                              void* d_out, int out_size) {
    const float* user_emb     = (const float*)d_in[0];
    const float* entity_emb   = (const float*)d_in[1];
    const float* relation_emb = (const float*)d_in[3];
    const float* disen        = (const float*)d_in[4];
    const float* usr_cls_w    = (const float*)d_in[5];
    const float* edge_imp     = (const float*)d_in[6];
    const float* im_vals      = (const float*)d_in[7];
    const float* icm_vals     = (const float*)d_in[8];
    const int*   edge_index   = (const int*)d_in[9];
    const int*   edge_type    = (const int*)d_in[10];
    const int*   im_rows      = (const int*)d_in[11];
    const int*   im_cols      = (const int*)d_in[12];
    const int*   icm_cls      = (const int*)d_in[13];
    const int*   icm_rows     = (const int*)d_in[14];
    const int*   icm_cols     = (const int*)d_in[15];

    float* out     = (float*)d_out;
    float* out_ent = out;
    float* out_usr = out + (size_t)N_ENTITIES * D;
    float* out_cor = out + (size_t)N_ENTITIES * D + (size_t)N_USERS * D;

    __half *p_ehA, *p_ehB;
    float *p_u;
    int *p_tsE, *p_tbE, *p_tsU, *p_tbU;
    cudaGetSymbolAddress((void**)&p_ehA, g_ehA);
    cudaGetSymbolAddress((void**)&p_ehB, g_ehB);
    cudaGetSymbolAddress((void**)&p_u, g_u);
    cudaGetSymbolAddress((void**)&p_tsE, g_tsE);
    cudaGetSymbolAddress((void**)&p_tbE, g_tbE);
    cudaGetSymbolAddress((void**)&p_tsU, g_tsU);
    cudaGetSymbolAddress((void**)&p_tbU, g_tbU);

    static cudaStream_t s1 = nullptr, s2 = nullptr;
    static cudaEvent_t ev_fork = nullptr, ev_prep = nullptr,
                       ev_ent0 = nullptr, ev_usr = nullptr;
    if (s1 == nullptr) {
        cudaStreamCreateWithFlags(&s1, cudaStreamNonBlocking);
        cudaStreamCreateWithFlags(&s2, cudaStreamNonBlocking);
        cudaEventCreateWithFlags(&ev_fork, cudaEventDisableTiming);
        cudaEventCreateWithFlags(&ev_prep, cudaEventDisableTiming);
        cudaEventCreateWithFlags(&ev_ent0, cudaEventDisableTiming);
        cudaEventCreateWithFlags(&ev_usr, cudaEventDisableTiming);
    }

    const int TPB = 256;
    unsigned ablocks  = (N_ENTITIES + N_USERS + TPB - 1) / TPB;
    unsigned eblocks  = (N_ENTITIES + TPB - 1) / TPB;
    unsigned ublocks  = (N_USERS + TPB - 1) / TPB;
    unsigned egblocks = (unsigned)(((long long)N_ENTITIES * 32 + TPB - 1) / TPB);
    unsigned ugblocks = (unsigned)(((long long)N_USERS * 32 + TPB - 1) / TPB);

    // ---- fork s1: convert+relsum, hop-0 att/ucls, cor ----
    cudaEventRecord(ev_fork, 0);
    cudaStreamWaitEvent(s1, ev_fork, 0);
    cudaStreamWaitEvent(s2, ev_fork, 0);
    convert_kernel<<<(CONV_N + TPB - 1) / TPB, TPB, 0, s1>>>(
        (const float2*)entity_emb, (__half2*)p_ehA, relation_emb);
    attucls0_kernel<<<ablocks, TPB, 0, s1>>>(entity_emb, user_emb, relation_emb, usr_cls_w);
    cor_kernel<<<1, 1, 0, s1>>>(disen, out_cor);
    cudaEventRecord(ev_prep, s1);

    // ---- main: ENTITY build pipeline (base 0) ----
    zero_range_kernel<<<(N_ENTITIES + TPB - 1) / TPB, TPB>>>(0, N_ENTITIES);
    count_edge_kernel<<<(N_EDGES + TPB - 1) / TPB, TPB>>>(edge_index);
    scanA_r_kernel<<<NT_ENT, SCAN_TILE>>>(0, N_ENTITIES, p_tsE);
    scanB_r_kernel<<<1, 128>>>(p_tsE, p_tbE, NT_ENT);
    scanC_r_kernel<<<NT_ENT, SCAN_TILE>>>(0, N_ENTITIES, p_tbE, 0);
    fill_edge_kernel<<<(N_EDGES + TPB - 1) / TPB, TPB>>>(
        edge_index, edge_index + N_EDGES, edge_type, edge_imp);

    // ---- s2: USER build pipeline (base = N_EDGES, constant) + user chain ----
    zero_range_kernel<<<(N_USERS * 2 + TPB - 1) / TPB, TPB, 0, s2>>>(IM_SEG0, N_USERS * 2);
    count_imicm_kernel<<<(NNZ_IMICM + TPB - 1) / TPB, TPB, 0, s2>>>(im_rows, icm_rows);
    scanA_r_kernel<<<NT_USR, SCAN_TILE, 0, s2>>>(IM_SEG0, N_USERS * 2, p_tsU);
    scanB_r_kernel<<<1, 128, 0, s2>>>(p_tsU, p_tbU, NT_USR);
    scanC_r_kernel<<<NT_USR, SCAN_TILE, 0, s2>>>(IM_SEG0, N_USERS * 2, p_tbU, N_EDGES);
    fill_imicm_kernel<<<(NNZ_IMICM + TPB - 1) / TPB, TPB, 0, s2>>>(
        im_rows, im_cols, im_vals, icm_rows, icm_cols, icm_cls, icm_vals);
    cudaStreamWaitEvent(s2, ev_prep, 0);
    usr_gather_kernel<true, false><<<ugblocks, TPB, 0, s2>>>(
        (const __half2*)p_ehA, p_u, (const float2*)user_emb, (float2*)out_usr);
    ucls_u_kernel<<<ublocks, TPB, 0, s2>>>(p_u, usr_cls_w);

    // ---- main: entity chain ----
    cudaStreamWaitEvent(0, ev_prep, 0);
    ent_gather_kernel<true, false><<<egblocks, TPB>>>(
        (const __half2*)p_ehA, relation_emb, (__half2*)p_ehB,
        (const float2*)entity_emb, (float2*)out_ent);
    cudaEventRecord(ev_ent0, 0);

    // ---- s2: hop-1 user gather (needs ehB + hop-1 ucls) ----
    cudaStreamWaitEvent(s2, ev_ent0, 0);
    usr_gather_kernel<false, true><<<ugblocks, TPB, 0, s2>>>(
        (const __half2*)p_ehB, p_u, nullptr, (float2*)out_usr);
    cudaEventRecord(ev_usr, s2);

    // ---- main: hop-1 entity att + gather ----
    att_e_kernel<<<eblocks, TPB>>>((const __half2*)p_ehB, relation_emb);
    ent_gather_kernel<false, true><<<egblocks, TPB>>>(
        (const __half2*)p_ehB, relation_emb, (__half2*)p_ehA,
        nullptr, (float2*)out_ent);

    // ---- join all ----
    cudaStreamWaitEvent(0, ev_usr, 0);
}